// round 2
// baseline (speedup 1.0000x reference)
#include <cuda_runtime.h>
#include <math.h>

// ---------------------------------------------------------------------------
// Problem constants (shapes fixed by the dataset)
// ---------------------------------------------------------------------------
#define DIM     1024
#define NH      8
#define Q_C     128
#define Q_NOPE  96
#define Q_ROPE  32
#define KV_C    128
#define K_NOPE  64
#define K_ROPE  64
#define V_HD    256
#define S_LEN   2048
#define BATCH   2
#define BSROWS  (BATCH * S_LEN)       // 4096
#define QK_D    128                   // Q_NOPE+Q_ROPE == K_NOPE+K_ROPE
#define EPSV    1e-8f

// ---------------------------------------------------------------------------
// Scratch (static device globals; no allocation allowed)
// ---------------------------------------------------------------------------
__device__ float g_cq_raw[BSROWS * Q_C];
__device__ float g_cq    [BSROWS * Q_C];
__device__ float g_ckvkr [BSROWS * (KV_C + K_ROPE)];
__device__ float g_ckv   [BSROWS * KV_C];
__device__ float g_qs    [BATCH * NH * S_LEN * QK_D];   // [B,H,S,128]
__device__ float g_ks    [BATCH * NH * S_LEN * QK_D];   // [B,H,S,128]
__device__ float g_vs    [BATCH * NH * S_LEN * V_HD];   // [B,H,S,256]
__device__ float g_attn  [BSROWS * (NH * V_HD)];        // [B*S, 2048]

// ---------------------------------------------------------------------------
// Generic 64x64x16 SGEMM, 256 threads, 4x4 per thread.
// EPI: 0 = plain to C param, 1 = g_cq_raw, 2 = g_ckvkr, 3 = Q scatter, 4 = KV scatter
// ASRC: 0 = A param, 1 = g_cq, 2 = g_ckv, 3 = g_attn
// ---------------------------------------------------------------------------
#define GBM 64
#define GBN 64
#define GBK 16

template <int EPI, int ASRC>
__global__ void __launch_bounds__(256) gemm_k(
    const float* __restrict__ Ap, const float* __restrict__ Bp,
    const float* __restrict__ bias, float* __restrict__ C,
    int M, int N, int K, int S)
{
    const float* A = (ASRC == 0) ? Ap : (ASRC == 1) ? g_cq : (ASRC == 2) ? g_ckv : g_attn;

    __shared__ float As[GBK][GBM + 4];   // +4 keeps float4 alignment on reads
    __shared__ float Bs[GBK][GBN];

    int tid = threadIdx.x;
    int tx = tid & 15, ty = tid >> 4;
    int m0 = blockIdx.y * GBM, n0 = blockIdx.x * GBN;

    int aRow  = tid >> 2;           // 0..63
    int aCol4 = (tid & 3) << 2;     // 0,4,8,12
    int bRow  = tid >> 4;           // 0..15
    int bCol4 = (tid & 15) << 2;

    float c[4][4] = {};

    for (int k0 = 0; k0 < K; k0 += GBK) {
        float4 av = *(const float4*)&A[(size_t)(m0 + aRow) * K + k0 + aCol4];
        float4 bv = *(const float4*)&Bp[(size_t)(k0 + bRow) * N + n0 + bCol4];
        As[aCol4 + 0][aRow] = av.x;
        As[aCol4 + 1][aRow] = av.y;
        As[aCol4 + 2][aRow] = av.z;
        As[aCol4 + 3][aRow] = av.w;
        *(float4*)&Bs[bRow][bCol4] = bv;
        __syncthreads();

#pragma unroll
        for (int kk = 0; kk < GBK; kk++) {
            float4 a = *(const float4*)&As[kk][ty << 2];
            float4 b = *(const float4*)&Bs[kk][tx << 2];
            c[0][0] += a.x * b.x; c[0][1] += a.x * b.y; c[0][2] += a.x * b.z; c[0][3] += a.x * b.w;
            c[1][0] += a.y * b.x; c[1][1] += a.y * b.y; c[1][2] += a.y * b.z; c[1][3] += a.y * b.w;
            c[2][0] += a.z * b.x; c[2][1] += a.z * b.y; c[2][2] += a.z * b.z; c[2][3] += a.z * b.w;
            c[3][0] += a.w * b.x; c[3][1] += a.w * b.y; c[3][2] += a.w * b.z; c[3][3] += a.w * b.w;
        }
        __syncthreads();
    }

#pragma unroll
    for (int i = 0; i < 4; i++) {
        int m = m0 + (ty << 2) + i;
        int b = m / S, s = m - b * S;
#pragma unroll
        for (int j = 0; j < 4; j++) {
            int n = n0 + (tx << 2) + j;
            float v = c[i][j] + bias[n];
            if (EPI == 0) {
                C[(size_t)m * N + n] = v;
            } else if (EPI == 1) {
                g_cq_raw[m * Q_C + n] = v;
            } else if (EPI == 2) {
                g_ckvkr[m * (KV_C + K_ROPE) + n] = v;
            } else if (EPI == 3) {
                int h, d;
                if (n < NH * Q_NOPE) { h = n / Q_NOPE; d = n % Q_NOPE; }
                else { int jj = n - NH * Q_NOPE; h = jj / Q_ROPE; d = Q_NOPE + (jj % Q_ROPE); }
                g_qs[(((size_t)b * NH + h) * S + s) * QK_D + d] = v;
            } else {
                if (n < NH * K_NOPE) {
                    int h = n / K_NOPE, d = n % K_NOPE;
                    g_ks[(((size_t)b * NH + h) * S + s) * QK_D + d] = v;
                } else {
                    int jj = n - NH * K_NOPE;
                    int h = jj / V_HD, d = jj % V_HD;
                    g_vs[(((size_t)b * NH + h) * S + s) * V_HD + d] = v;
                }
            }
        }
    }
}

// ---------------------------------------------------------------------------
// RMSNorm for cq (128 cols). One block (128 thr) per row.
// ---------------------------------------------------------------------------
__global__ void rmsnorm_q_k(const float* __restrict__ w)
{
    int row = blockIdx.x, t = threadIdx.x;
    float v = g_cq_raw[row * Q_C + t];
    float ss = v * v;
#pragma unroll
    for (int off = 16; off > 0; off >>= 1) ss += __shfl_xor_sync(0xffffffffu, ss, off);
    __shared__ float s4[4];
    if ((t & 31) == 0) s4[t >> 5] = ss;
    __syncthreads();
    float tot = s4[0] + s4[1] + s4[2] + s4[3];
    float r = rsqrtf(tot * (1.0f / Q_C) + EPSV);
    g_cq[row * Q_C + t] = w[t] * v * r;
}

// ---------------------------------------------------------------------------
// KV post: RMSNorm first 128 cols of ckv_kr -> g_ckv; RoPE last 64 cols
// -> broadcast into g_ks[:, :, :, 64:128] for all heads.
// ---------------------------------------------------------------------------
__global__ void kv_post_k(const float* __restrict__ kvw, const int* __restrict__ pos_ids, int S)
{
    int row = blockIdx.x, t = threadIdx.x;
    const float* src = &g_ckvkr[row * (KV_C + K_ROPE)];
    float v = src[t];
    float ss = v * v;
#pragma unroll
    for (int off = 16; off > 0; off >>= 1) ss += __shfl_xor_sync(0xffffffffu, ss, off);
    __shared__ float s4[4];
    if ((t & 31) == 0) s4[t >> 5] = ss;
    __syncthreads();
    float tot = s4[0] + s4[1] + s4[2] + s4[3];
    float r = rsqrtf(tot * (1.0f / KV_C) + EPSV);
    g_ckv[row * KV_C + t] = kvw[t] * v * r;

    if (t < K_ROPE / 2) {
        int i = t;
        float xe = src[KV_C + 2 * i];
        float xo = src[KV_C + 2 * i + 1];
        float p = (float)pos_ids[row];
        float inv = expf(-((float)(2 * i) / (float)K_ROPE) * 9.210340371976184f); // ln(10000)
        float sn, cs;
        sincosf(p * inv, &sn, &cs);
        float re = xe * cs - xo * sn;
        float ro = xe * sn + xo * cs;
        int b = row / S, s = row - b * S;
#pragma unroll
        for (int h = 0; h < NH; h++) {
            size_t base = (((size_t)b * NH + h) * S + s) * QK_D + K_NOPE;
            g_ks[base + 2 * i]     = re;
            g_ks[base + 2 * i + 1] = ro;
        }
    }
}

// ---------------------------------------------------------------------------
// RoPE on the rope half of Q (dims 96..127, head_dim 32). One thread per pair.
// ---------------------------------------------------------------------------
__global__ void rope_q_k(const int* __restrict__ pos_ids, int S, int total)
{
    int idx = blockIdx.x * blockDim.x + threadIdx.x;
    if (idx >= total) return;
    int i = idx & 15;          // pair index (16 pairs)
    int bhs = idx >> 4;        // (b*NH + h)*S + s
    int s = bhs % S;
    int bh = bhs / S;
    int b = bh / NH;
    float p = (float)pos_ids[b * S + s];
    float inv = expf(-((float)(2 * i) / (float)Q_ROPE) * 9.210340371976184f);
    float sn, cs;
    sincosf(p * inv, &sn, &cs);
    size_t base = (size_t)bhs * QK_D + Q_NOPE;
    float xe = g_qs[base + 2 * i];
    float xo = g_qs[base + 2 * i + 1];
    g_qs[base + 2 * i]     = xe * cs - xo * sn;
    g_qs[base + 2 * i + 1] = xe * sn + xo * cs;
}

// ---------------------------------------------------------------------------
// Flash-style attention. Grid (S/32, NH, B), 256 threads (8 warps).
// Each warp owns 4 query rows; lane owns d = lane*8..lane*8+7 of the 256-dim O.
// K tiles of 32 keys staged in padded smem; V streamed from gmem (L2-resident).
// ---------------------------------------------------------------------------
#define AQ 32            // queries per block
#define AK 32            // keys per tile
#define KPAD 132         // K row stride in smem (floats): 132 = 33 float4s, conflict-free

__global__ void __launch_bounds__(256) attn_k(int S)
{
    __shared__ float sQ[AQ * QK_D];       // 16 KB
    __shared__ float sK[AK * KPAD];       // 16.9 KB
    __shared__ float sP[AQ * AK];         // 4 KB

    int qt = blockIdx.x, h = blockIdx.y, b = blockIdx.z;
    int tid = threadIdx.x;
    int warp = tid >> 5, lane = tid & 31;

    const float* Qg = g_qs + (((size_t)b * NH + h) * S + (size_t)qt * AQ) * QK_D;
    const float* Kg = g_ks + (((size_t)b * NH + h) * S) * QK_D;
    const float* Vg = g_vs + (((size_t)b * NH + h) * S) * V_HD;

    // load Q tile (32x128 = 1024 float4)
#pragma unroll
    for (int r = 0; r < 4; r++) {
        int f = r * 256 + tid;
        ((float4*)sQ)[f] = ((const float4*)Qg)[f];
    }

    const float scale = 0.08838834764831845f;   // 1/sqrt(128)
    float m_i[4], l_i[4], acc[4][8];
#pragma unroll
    for (int qq = 0; qq < 4; qq++) {
        m_i[qq] = -1e30f; l_i[qq] = 0.f;
#pragma unroll
        for (int jj = 0; jj < 8; jj++) acc[qq][jj] = 0.f;
    }

    int ntiles = S / AK;
    for (int kt = 0; kt < ntiles; kt++) {
        __syncthreads();   // previous iter's reads of sK/sP complete
        // load K tile: 32 rows x 128 -> sK[k*KPAD + i]
#pragma unroll
        for (int r = 0; r < 4; r++) {
            int f = r * 256 + tid;          // float4 index, 1024 total
            int k = f >> 5;                 // 32 float4 per row
            int i4 = (f & 31) << 2;
            float4 v = *(const float4*)&Kg[(size_t)(kt * AK + k) * QK_D + i4];
            *(float4*)&sK[k * KPAD + i4] = v;
        }
        __syncthreads();

        // scores: lane computes key k=lane for its warp's 4 query rows
        float sacc[4] = {0.f, 0.f, 0.f, 0.f};
#pragma unroll 8
        for (int i4 = 0; i4 < 32; i4++) {
            float4 kv = *(const float4*)&sK[lane * KPAD + (i4 << 2)];
#pragma unroll
            for (int qq = 0; qq < 4; qq++) {
                float4 qv = *(const float4*)&sQ[((warp << 2) + qq) * QK_D + (i4 << 2)];
                sacc[qq] += qv.x * kv.x + qv.y * kv.y + qv.z * kv.z + qv.w * kv.w;
            }
        }

        // online softmax update (per warp, per row)
#pragma unroll
        for (int qq = 0; qq < 4; qq++) {
            float sv = sacc[qq] * scale;
            float tm = sv;
#pragma unroll
            for (int off = 16; off > 0; off >>= 1)
                tm = fmaxf(tm, __shfl_xor_sync(0xffffffffu, tm, off));
            float mn = fmaxf(m_i[qq], tm);
            float p = __expf(sv - mn);
            float ps = p;
#pragma unroll
            for (int off = 16; off > 0; off >>= 1)
                ps += __shfl_xor_sync(0xffffffffu, ps, off);
            float corr = __expf(m_i[qq] - mn);
            l_i[qq] = l_i[qq] * corr + ps;
            m_i[qq] = mn;
            sP[((warp << 2) + qq) * AK + lane] = p;
#pragma unroll
            for (int jj = 0; jj < 8; jj++) acc[qq][jj] *= corr;
        }
        __syncwarp();

        // PV: O[q][d] += p[q][k] * V[k][d], V from gmem (coalesced float4, L2-hot)
        const float* Vt = Vg + (size_t)kt * AK * V_HD;
#pragma unroll 4
        for (int k = 0; k < AK; k++) {
            float4 v0 = *(const float4*)&Vt[k * V_HD + lane * 8];
            float4 v1 = *(const float4*)&Vt[k * V_HD + lane * 8 + 4];
#pragma unroll
            for (int qq = 0; qq < 4; qq++) {
                float p = sP[((warp << 2) + qq) * AK + k];
                acc[qq][0] += p * v0.x; acc[qq][1] += p * v0.y;
                acc[qq][2] += p * v0.z; acc[qq][3] += p * v0.w;
                acc[qq][4] += p * v1.x; acc[qq][5] += p * v1.y;
                acc[qq][6] += p * v1.z; acc[qq][7] += p * v1.w;
            }
        }
    }

    // epilogue: normalize, write to g_attn[(b*S + q)*2048 + h*256 + d]
#pragma unroll
    for (int qq = 0; qq < 4; qq++) {
        int qrow = qt * AQ + (warp << 2) + qq;
        float invl = 1.0f / l_i[qq];
        float4 o0 = make_float4(acc[qq][0] * invl, acc[qq][1] * invl,
                                acc[qq][2] * invl, acc[qq][3] * invl);
        float4 o1 = make_float4(acc[qq][4] * invl, acc[qq][5] * invl,
                                acc[qq][6] * invl, acc[qq][7] * invl);
        size_t base = ((size_t)b * S + qrow) * (NH * V_HD) + h * V_HD + lane * 8;
        *(float4*)&g_attn[base]     = o0;
        *(float4*)&g_attn[base + 4] = o1;
    }
}

// ---------------------------------------------------------------------------
// Launch
// ---------------------------------------------------------------------------
extern "C" void kernel_launch(void* const* d_in, const int* in_sizes, int n_in,
                              void* d_out, int out_size)
{
    const float* x         = (const float*)d_in[0];
    const int*   pos       = (const int*)  d_in[1];
    const float* w_dq_w    = (const float*)d_in[2];
    const float* w_dq_b    = (const float*)d_in[3];
    const float* q_norm_w  = (const float*)d_in[4];
    const float* w_uq_qr_w = (const float*)d_in[5];
    const float* w_uq_qr_b = (const float*)d_in[6];
    const float* w_dkv_w   = (const float*)d_in[7];
    const float* w_dkv_b   = (const float*)d_in[8];
    const float* kv_norm_w = (const float*)d_in[9];
    const float* w_ukv_w   = (const float*)d_in[10];
    const float* w_ukv_b   = (const float*)d_in[11];
    const float* w_o_w     = (const float*)d_in[12];
    const float* w_o_b     = (const float*)d_in[13];
    float* out = (float*)d_out;

    const int M = in_sizes[0] / DIM;   // B*S = 4096
    const int S = S_LEN;
    const int B = M / S;

    dim3 blk(256);

    // Q path: cq_raw = x @ w_dq + b
    gemm_k<1, 0><<<dim3(Q_C / GBN, M / GBM), blk>>>(x, w_dq_w, w_dq_b, nullptr, M, Q_C, DIM, S);
    rmsnorm_q_k<<<M, 128>>>(q_norm_w);
    // q = cq @ w_uq_qr + b  -> scatter into g_qs
    gemm_k<3, 1><<<dim3((NH * QK_D) / GBN, M / GBM), blk>>>(nullptr, w_uq_qr_w, w_uq_qr_b, nullptr, M, NH * QK_D, Q_C, S);
    // RoPE on q_rope
    {
        int total = B * NH * S * (Q_ROPE / 2);
        rope_q_k<<<(total + 255) / 256, 256>>>(pos, S, total);
    }

    // KV path: ckv_kr = x @ w_dkv_kr + b
    gemm_k<2, 0><<<dim3((KV_C + K_ROPE) / GBN, M / GBM), blk>>>(x, w_dkv_w, w_dkv_b, nullptr, M, KV_C + K_ROPE, DIM, S);
    kv_post_k<<<M, 128>>>(kv_norm_w, pos, S);
    // kv = ckv @ w_uk_uv + b -> scatter into g_ks (nope part) and g_vs
    gemm_k<4, 2><<<dim3((NH * (K_NOPE + V_HD)) / GBN, M / GBM), blk>>>(nullptr, w_ukv_w, w_ukv_b, nullptr, M, NH * (K_NOPE + V_HD), KV_C, S);

    // attention
    attn_k<<<dim3(S / AQ, NH, B), blk>>>(S);

    // output projection: out = attn @ w_o + b
    gemm_k<0, 3><<<dim3(DIM / GBN, M / GBM), blk>>>(nullptr, w_o_w, w_o_b, out, M, DIM, NH * V_HD, S);
}

// round 8
// speedup vs baseline: 5.8904x; 5.8904x over previous
#include <cuda_runtime.h>
#include <cuda_fp16.h>
#include <cstdint>
#include <math.h>

typedef unsigned int u32;

// ---------------------------------------------------------------------------
// Problem constants
// ---------------------------------------------------------------------------
#define DIM     1024
#define NH      8
#define Q_C     128
#define Q_NOPE  96
#define Q_ROPE  32
#define KV_C    128
#define K_NOPE  64
#define K_ROPE  64
#define V_HD    256
#define S_LEN   2048
#define BATCH   2
#define BSROWS  (BATCH * S_LEN)       // 4096
#define QK_D    128
#define EPSV    1e-8f
#define SCALE   0.08838834764831845f  // 1/sqrt(128)

// ---------------------------------------------------------------------------
// Scratch (static device globals; no allocation allowed)
// ---------------------------------------------------------------------------
__device__ __half hx    [BSROWS * DIM];
__device__ __half hw_dq [DIM * Q_C];
__device__ __half hw_uq [Q_C * (NH * QK_D)];
__device__ __half hw_dkv[DIM * (KV_C + K_ROPE)];
__device__ __half hw_ukv[KV_C * (NH * (K_NOPE + V_HD))];
__device__ __half hw_o  [(NH * V_HD) * DIM];

__device__ float  g_cq_raw[BSROWS * Q_C];
__device__ __half g_cq_h  [BSROWS * Q_C];
__device__ float  g_ckvkr [BSROWS * (KV_C + K_ROPE)];
__device__ __half g_ckv_h [BSROWS * KV_C];
__device__ __half g_qs    [BATCH * NH * S_LEN * QK_D];   // scaled q, [B,H,S,128]
__device__ __half g_ks    [BATCH * NH * S_LEN * QK_D];
__device__ __half g_vs    [BATCH * NH * S_LEN * V_HD];
__device__ __half g_attn_h[BSROWS * (NH * V_HD)];

// ---------------------------------------------------------------------------
// PTX helpers
// ---------------------------------------------------------------------------
__device__ __forceinline__ u32 smem_a(const void* p) {
    return (u32)__cvta_generic_to_shared(p);
}
__device__ __forceinline__ void ldsm4(u32* r, u32 a) {
    asm volatile("ldmatrix.sync.aligned.m8n8.x4.shared.b16 {%0,%1,%2,%3},[%4];"
                 : "=r"(r[0]), "=r"(r[1]), "=r"(r[2]), "=r"(r[3]) : "r"(a));
}
__device__ __forceinline__ void ldsm4t(u32* r, u32 a) {
    asm volatile("ldmatrix.sync.aligned.m8n8.x4.trans.shared.b16 {%0,%1,%2,%3},[%4];"
                 : "=r"(r[0]), "=r"(r[1]), "=r"(r[2]), "=r"(r[3]) : "r"(a));
}
__device__ __forceinline__ void mma16816(float* d, const u32* a, const u32* b) {
    asm volatile("mma.sync.aligned.m16n8k16.row.col.f32.f16.f16.f32 "
                 "{%0,%1,%2,%3},{%4,%5,%6,%7},{%8,%9},{%0,%1,%2,%3};"
                 : "+f"(d[0]), "+f"(d[1]), "+f"(d[2]), "+f"(d[3])
                 : "r"(a[0]), "r"(a[1]), "r"(a[2]), "r"(a[3]), "r"(b[0]), "r"(b[1]));
}

// ---------------------------------------------------------------------------
// fp32 -> fp16 conversion (templated destination)
// ---------------------------------------------------------------------------
template <int DST>
__global__ void cvt_k(const float* __restrict__ src, int n8)
{
    __half* dst = DST == 0 ? hx : DST == 1 ? hw_dq : DST == 2 ? hw_uq :
                  DST == 3 ? hw_dkv : DST == 4 ? hw_ukv : hw_o;
    int i = blockIdx.x * blockDim.x + threadIdx.x;
    if (i >= n8) return;
    float4 f0 = ((const float4*)src)[2 * i];
    float4 f1 = ((const float4*)src)[2 * i + 1];
    union { __half2 h[4]; int4 v; } u;
    u.h[0] = __floats2half2_rn(f0.x, f0.y);
    u.h[1] = __floats2half2_rn(f0.z, f0.w);
    u.h[2] = __floats2half2_rn(f1.x, f1.y);
    u.h[3] = __floats2half2_rn(f1.z, f1.w);
    ((int4*)dst)[i] = u.v;
}

// ---------------------------------------------------------------------------
// Epilogue store
// EPI: 0=out fp32, 1=g_cq_raw, 2=g_ckvkr, 3=Q scatter(scaled,half), 4=KV scatter(half)
// ---------------------------------------------------------------------------
template <int EPI>
__device__ __forceinline__ void epi_store(int m, int n, float v, float* C, int N)
{
    int b = m / S_LEN, s = m - b * S_LEN;
    if (EPI == 0) {
        C[(size_t)m * N + n] = v;
    } else if (EPI == 1) {
        g_cq_raw[m * Q_C + n] = v;
    } else if (EPI == 2) {
        g_ckvkr[m * (KV_C + K_ROPE) + n] = v;
    } else if (EPI == 3) {
        int h, d;
        if (n < NH * Q_NOPE) { h = n / Q_NOPE; d = n % Q_NOPE; }
        else { int j = n - NH * Q_NOPE; h = j / Q_ROPE; d = Q_NOPE + (j % Q_ROPE); }
        g_qs[(((size_t)b * NH + h) * S_LEN + s) * QK_D + d] = __float2half(v * SCALE);
    } else {
        if (n < NH * K_NOPE) {
            int h = n / K_NOPE, d = n % K_NOPE;
            g_ks[(((size_t)b * NH + h) * S_LEN + s) * QK_D + d] = __float2half(v);
        } else {
            int j = n - NH * K_NOPE;
            int h = j / V_HD, d = j % V_HD;
            g_vs[(((size_t)b * NH + h) * S_LEN + s) * V_HD + d] = __float2half(v);
        }
    }
}

// ---------------------------------------------------------------------------
// HGEMM: 64x64x32 tile, 128 threads (4 warps 2x2), warp tile 32x32, fp16 mma.
// ---------------------------------------------------------------------------
#define HBM 64
#define HBN 64
#define HBK 32
#define ALD 40   // halfs: 80B stride -> conflict-free ldmatrix
#define BLD 72   // halfs: 144B stride

template <int EPI, int ASRC>
__global__ void __launch_bounds__(128) hgemm_k(const float* __restrict__ bias,
                                               float* __restrict__ C, int N, int K)
{
    const __half* A = ASRC == 0 ? hx : ASRC == 1 ? g_cq_h : ASRC == 2 ? g_ckv_h : g_attn_h;
    const __half* B = EPI == 1 ? hw_dq : EPI == 3 ? hw_uq : EPI == 2 ? hw_dkv :
                      EPI == 4 ? hw_ukv : hw_o;

    __shared__ __half sA[HBM * ALD];
    __shared__ __half sB[HBK * BLD];

    int tid = threadIdx.x, warp = tid >> 5, lane = tid & 31;
    int m0 = blockIdx.y * HBM, n0 = blockIdx.x * HBN;
    int wm = (warp >> 1) * 32, wn = (warp & 1) * 32;

    float acc[2][4][4];
#pragma unroll
    for (int i = 0; i < 2; i++)
#pragma unroll
        for (int j = 0; j < 4; j++)
#pragma unroll
            for (int k = 0; k < 4; k++) acc[i][j][k] = 0.f;

    int ar = tid >> 2, ac = (tid & 3) * 8;
    int br = tid >> 3, bc = (tid & 7) * 8;

    int4 av0 = *(const int4*)&A[(size_t)(m0 + ar) * K + ac];
    int4 av1 = *(const int4*)&A[(size_t)(m0 + 32 + ar) * K + ac];
    int4 bv0 = *(const int4*)&B[(size_t)br * N + n0 + bc];
    int4 bv1 = *(const int4*)&B[(size_t)(16 + br) * N + n0 + bc];

    for (int k0 = 0; k0 < K; k0 += HBK) {
        __syncthreads();
        *(int4*)&sA[ar * ALD + ac] = av0;
        *(int4*)&sA[(32 + ar) * ALD + ac] = av1;
        *(int4*)&sB[br * BLD + bc] = bv0;
        *(int4*)&sB[(16 + br) * BLD + bc] = bv1;
        __syncthreads();
        int kn = k0 + HBK;
        if (kn < K) {
            av0 = *(const int4*)&A[(size_t)(m0 + ar) * K + kn + ac];
            av1 = *(const int4*)&A[(size_t)(m0 + 32 + ar) * K + kn + ac];
            bv0 = *(const int4*)&B[(size_t)(kn + br) * N + n0 + bc];
            bv1 = *(const int4*)&B[(size_t)(kn + 16 + br) * N + n0 + bc];
        }
#pragma unroll
        for (int ks = 0; ks < 2; ks++) {
            u32 a[2][4], bm[4][2];
#pragma unroll
            for (int mi = 0; mi < 2; mi++)
                ldsm4(a[mi], smem_a(&sA[(wm + mi * 16 + (lane & 15)) * ALD + ks * 16 + (lane >> 4) * 8]));
#pragma unroll
            for (int njp = 0; njp < 2; njp++) {
                u32 r[4];
                ldsm4t(r, smem_a(&sB[(ks * 16 + ((lane >> 3) & 1) * 8 + (lane & 7)) * BLD
                                     + wn + njp * 16 + (lane >> 4) * 8]));
                bm[njp * 2][0] = r[0]; bm[njp * 2][1] = r[1];
                bm[njp * 2 + 1][0] = r[2]; bm[njp * 2 + 1][1] = r[3];
            }
#pragma unroll
            for (int mi = 0; mi < 2; mi++)
#pragma unroll
                for (int nj = 0; nj < 4; nj++)
                    mma16816(acc[mi][nj], a[mi], bm[nj]);
        }
    }

#pragma unroll
    for (int mi = 0; mi < 2; mi++)
#pragma unroll
        for (int nj = 0; nj < 4; nj++) {
            int row = m0 + wm + mi * 16 + (lane >> 2);
            int col = n0 + wn + nj * 8 + 2 * (lane & 3);
            epi_store<EPI>(row,     col,     acc[mi][nj][0] + bias[col],     C, N);
            epi_store<EPI>(row,     col + 1, acc[mi][nj][1] + bias[col + 1], C, N);
            epi_store<EPI>(row + 8, col,     acc[mi][nj][2] + bias[col],     C, N);
            epi_store<EPI>(row + 8, col + 1, acc[mi][nj][3] + bias[col + 1], C, N);
        }
}

// ---------------------------------------------------------------------------
// RMSNorm q: fp32 in -> half out
// ---------------------------------------------------------------------------
__global__ void rmsnorm_q_k(const float* __restrict__ w)
{
    int row = blockIdx.x, t = threadIdx.x;
    float v = g_cq_raw[row * Q_C + t];
    float ss = v * v;
#pragma unroll
    for (int off = 16; off > 0; off >>= 1) ss += __shfl_xor_sync(0xffffffffu, ss, off);
    __shared__ float s4[4];
    if ((t & 31) == 0) s4[t >> 5] = ss;
    __syncthreads();
    float tot = s4[0] + s4[1] + s4[2] + s4[3];
    float r = rsqrtf(tot * (1.0f / Q_C) + EPSV);
    g_cq_h[row * Q_C + t] = __float2half(w[t] * v * r);
}

// ---------------------------------------------------------------------------
// KV post: RMSNorm ckv -> half; RoPE k_rope -> broadcast (half) to all heads.
// ---------------------------------------------------------------------------
__global__ void kv_post_k(const float* __restrict__ kvw, const int* __restrict__ pos_ids)
{
    int row = blockIdx.x, t = threadIdx.x;
    const float* src = &g_ckvkr[row * (KV_C + K_ROPE)];
    float v = src[t];
    float ss = v * v;
#pragma unroll
    for (int off = 16; off > 0; off >>= 1) ss += __shfl_xor_sync(0xffffffffu, ss, off);
    __shared__ float s4[4];
    if ((t & 31) == 0) s4[t >> 5] = ss;
    __syncthreads();
    float tot = s4[0] + s4[1] + s4[2] + s4[3];
    float r = rsqrtf(tot * (1.0f / KV_C) + EPSV);
    g_ckv_h[row * KV_C + t] = __float2half(kvw[t] * v * r);

    if (t < K_ROPE / 2) {
        int i = t;
        float xe = src[KV_C + 2 * i];
        float xo = src[KV_C + 2 * i + 1];
        float p = (float)pos_ids[row];
        float inv = expf(-((float)(2 * i) / (float)K_ROPE) * 9.210340371976184f);
        float sn, cs;
        sincosf(p * inv, &sn, &cs);
        __half re = __float2half(xe * cs - xo * sn);
        __half ro = __float2half(xe * sn + xo * cs);
        int b = row / S_LEN, s = row - b * S_LEN;
#pragma unroll
        for (int h = 0; h < NH; h++) {
            size_t base = (((size_t)b * NH + h) * S_LEN + s) * QK_D + K_NOPE;
            g_ks[base + 2 * i]     = re;
            g_ks[base + 2 * i + 1] = ro;
        }
    }
}

// ---------------------------------------------------------------------------
// RoPE on Q rope half (dims 96..127), half in-place. (Q already scaled.)
// ---------------------------------------------------------------------------
__global__ void rope_q_k(const int* __restrict__ pos_ids, int total)
{
    int idx = blockIdx.x * blockDim.x + threadIdx.x;
    if (idx >= total) return;
    int i = idx & 15;
    int bhs = idx >> 4;
    int s = bhs % S_LEN;
    int bh = bhs / S_LEN;
    int b = bh / NH;
    float p = (float)pos_ids[b * S_LEN + s];
    float inv = expf(-((float)(2 * i) / (float)Q_ROPE) * 9.210340371976184f);
    float sn, cs;
    sincosf(p * inv, &sn, &cs);
    size_t base = (size_t)bhs * QK_D + Q_NOPE;
    float xe = __half2float(g_qs[base + 2 * i]);
    float xo = __half2float(g_qs[base + 2 * i + 1]);
    g_qs[base + 2 * i]     = __float2half(xe * cs - xo * sn);
    g_qs[base + 2 * i + 1] = __float2half(xe * sn + xo * cs);
}

// ---------------------------------------------------------------------------
// Flash attention, fp16 mma. Grid (32, 8, 2), 256 threads = 8 warps:
// warp = row-group (4 x 16 rows) x d-half (2 x 128). 32-key chunks,
// register-double-buffered K/V. Scores recomputed per d-half.
// ---------------------------------------------------------------------------
#define AQT 64
#define ACH 32
#define QLD 136
#define KLD 136
#define VLD 264

__global__ void __launch_bounds__(256) attn_h_k()
{
    __shared__ __half sQ[AQT * QLD];
    __shared__ __half sK[ACH * KLD];
    __shared__ __half sV[ACH * VLD];

    int tid = threadIdx.x, warp = tid >> 5, lane = tid & 31;
    int rg = warp & 3, dh = warp >> 2;
    int qt = blockIdx.x, h = blockIdx.y, b = blockIdx.z;

    const __half* Qg = g_qs + (((size_t)b * NH + h) * S_LEN + (size_t)qt * AQT) * QK_D;
    const __half* Kg = g_ks + ((size_t)b * NH + h) * S_LEN * QK_D;
    const __half* Vg = g_vs + ((size_t)b * NH + h) * S_LEN * V_HD;

    // load Q tile: 64 rows x 128 cols = 1024 int4
#pragma unroll
    for (int r = 0; r < 4; r++) {
        int idx = r * 256 + tid, row = idx >> 4, c = (idx & 15) * 8;
        *(int4*)&sQ[row * QLD + c] = *(const int4*)&Qg[row * QK_D + c];
    }

    float m_i[2] = { -1e30f, -1e30f }, l_i[2] = { 0.f, 0.f };
    float o[16][4];
#pragma unroll
    for (int nt = 0; nt < 16; nt++)
#pragma unroll
        for (int j = 0; j < 4; j++) o[nt][j] = 0.f;

    int4 kr[2], vr[4];
#pragma unroll
    for (int r = 0; r < 2; r++) {
        int idx = r * 256 + tid;
        kr[r] = *(const int4*)&Kg[(size_t)(idx >> 4) * QK_D + (idx & 15) * 8];
    }
#pragma unroll
    for (int r = 0; r < 4; r++) {
        int idx = r * 256 + tid;
        vr[r] = *(const int4*)&Vg[(size_t)(idx >> 5) * V_HD + (idx & 31) * 8];
    }
#pragma unroll
    for (int r = 0; r < 2; r++) {
        int idx = r * 256 + tid;
        *(int4*)&sK[(idx >> 4) * KLD + (idx & 15) * 8] = kr[r];
    }
#pragma unroll
    for (int r = 0; r < 4; r++) {
        int idx = r * 256 + tid;
        *(int4*)&sV[(idx >> 5) * VLD + (idx & 31) * 8] = vr[r];
    }
    __syncthreads();

    const int NCH = S_LEN / ACH;
    for (int kc = 0; kc < NCH; kc++) {
        if (kc + 1 < NCH) {
            const __half* Kn = Kg + (size_t)(kc + 1) * ACH * QK_D;
            const __half* Vn = Vg + (size_t)(kc + 1) * ACH * V_HD;
#pragma unroll
            for (int r = 0; r < 2; r++) {
                int idx = r * 256 + tid;
                kr[r] = *(const int4*)&Kn[(size_t)(idx >> 4) * QK_D + (idx & 15) * 8];
            }
#pragma unroll
            for (int r = 0; r < 4; r++) {
                int idx = r * 256 + tid;
                vr[r] = *(const int4*)&Vn[(size_t)(idx >> 5) * V_HD + (idx & 31) * 8];
            }
        }

        // ---- scores S = Q K^T (pre-scaled Q) ----
        float sc[4][4];
#pragma unroll
        for (int nj = 0; nj < 4; nj++)
#pragma unroll
            for (int j = 0; j < 4; j++) sc[nj][j] = 0.f;

#pragma unroll
        for (int ks = 0; ks < 8; ks++) {
            u32 a[4], bm[4][2];
            ldsm4(a, smem_a(&sQ[(rg * 16 + (lane & 15)) * QLD + ks * 16 + (lane >> 4) * 8]));
#pragma unroll
            for (int njp = 0; njp < 2; njp++) {
                u32 r[4];
                ldsm4(r, smem_a(&sK[(njp * 16 + ((lane >> 4) & 1) * 8 + (lane & 7)) * KLD
                                    + ks * 16 + ((lane >> 3) & 1) * 8]));
                bm[njp * 2][0] = r[0]; bm[njp * 2][1] = r[1];
                bm[njp * 2 + 1][0] = r[2]; bm[njp * 2 + 1][1] = r[3];
            }
#pragma unroll
            for (int nj = 0; nj < 4; nj++) mma16816(sc[nj], a, bm[nj]);
        }

        // ---- online softmax ----
        u32 p2[2][4];
#pragma unroll
        for (int i = 0; i < 2; i++) {
            float mx = -1e30f;
#pragma unroll
            for (int nj = 0; nj < 4; nj++)
                mx = fmaxf(mx, fmaxf(sc[nj][2 * i], sc[nj][2 * i + 1]));
            mx = fmaxf(mx, __shfl_xor_sync(0xffffffffu, mx, 1));
            mx = fmaxf(mx, __shfl_xor_sync(0xffffffffu, mx, 2));
            float mn = fmaxf(m_i[i], mx);
            float rs = 0.f;
#pragma unroll
            for (int nj = 0; nj < 4; nj++) {
                float p0 = __expf(sc[nj][2 * i] - mn);
                float p1 = __expf(sc[nj][2 * i + 1] - mn);
                rs += p0 + p1;
                __half2 hh = __floats2half2_rn(p0, p1);
                p2[i][nj] = *(u32*)&hh;
            }
            rs += __shfl_xor_sync(0xffffffffu, rs, 1);
            rs += __shfl_xor_sync(0xffffffffu, rs, 2);
            float corr = __expf(m_i[i] - mn);
            l_i[i] = l_i[i] * corr + rs;
            m_i[i] = mn;
#pragma unroll
            for (int nt = 0; nt < 16; nt++) {
                o[nt][2 * i] *= corr; o[nt][2 * i + 1] *= corr;
            }
        }

        // ---- O += P V ----
#pragma unroll
        for (int kt = 0; kt < 2; kt++) {
            u32 a[4] = { p2[0][2 * kt], p2[1][2 * kt], p2[0][2 * kt + 1], p2[1][2 * kt + 1] };
#pragma unroll
            for (int njp = 0; njp < 8; njp++) {
                u32 r[4];
                ldsm4t(r, smem_a(&sV[(kt * 16 + ((lane >> 3) & 1) * 8 + (lane & 7)) * VLD
                                     + dh * 128 + njp * 16 + (lane >> 4) * 8]));
                u32 b0[2] = { r[0], r[1] }, b1[2] = { r[2], r[3] };
                mma16816(o[njp * 2], a, b0);
                mma16816(o[njp * 2 + 1], a, b1);
            }
        }

        __syncthreads();
        if (kc + 1 < NCH) {
#pragma unroll
            for (int r = 0; r < 2; r++) {
                int idx = r * 256 + tid;
                *(int4*)&sK[(idx >> 4) * KLD + (idx & 15) * 8] = kr[r];
            }
#pragma unroll
            for (int r = 0; r < 4; r++) {
                int idx = r * 256 + tid;
                *(int4*)&sV[(idx >> 5) * VLD + (idx & 31) * 8] = vr[r];
            }
        }
        __syncthreads();
    }

    // ---- epilogue ----
#pragma unroll
    for (int i = 0; i < 2; i++) {
        float inv = 1.f / l_i[i];
        int row = qt * AQT + rg * 16 + (lane >> 2) + i * 8;
        size_t base = ((size_t)b * S_LEN + row) * (NH * V_HD) + h * V_HD + dh * 128;
#pragma unroll
        for (int nt = 0; nt < 16; nt++) {
            __half2 hh = __floats2half2_rn(o[nt][2 * i] * inv, o[nt][2 * i + 1] * inv);
            *(__half2*)&g_attn_h[base + nt * 8 + 2 * (lane & 3)] = hh;
        }
    }
}

// ---------------------------------------------------------------------------
// Launch
// ---------------------------------------------------------------------------
extern "C" void kernel_launch(void* const* d_in, const int* in_sizes, int n_in,
                              void* d_out, int out_size)
{
    const float* x         = (const float*)d_in[0];
    const int*   pos       = (const int*)  d_in[1];
    const float* w_dq_w    = (const float*)d_in[2];
    const float* w_dq_b    = (const float*)d_in[3];
    const float* q_norm_w  = (const float*)d_in[4];
    const float* w_uq_qr_w = (const float*)d_in[5];
    const float* w_uq_qr_b = (const float*)d_in[6];
    const float* w_dkv_w   = (const float*)d_in[7];
    const float* w_dkv_b   = (const float*)d_in[8];
    const float* kv_norm_w = (const float*)d_in[9];
    const float* w_ukv_w   = (const float*)d_in[10];
    const float* w_ukv_b   = (const float*)d_in[11];
    const float* w_o_w     = (const float*)d_in[12];
    const float* w_o_b     = (const float*)d_in[13];
    float* out = (float*)d_out;

    // fp32 -> fp16 conversions
    cvt_k<0><<<(BSROWS * DIM / 8 + 255) / 256, 256>>>(x, BSROWS * DIM / 8);
    cvt_k<1><<<(DIM * Q_C / 8 + 255) / 256, 256>>>(w_dq_w, DIM * Q_C / 8);
    cvt_k<2><<<(Q_C * NH * QK_D / 8 + 255) / 256, 256>>>(w_uq_qr_w, Q_C * NH * QK_D / 8);
    cvt_k<3><<<(DIM * (KV_C + K_ROPE) / 8 + 255) / 256, 256>>>(w_dkv_w, DIM * (KV_C + K_ROPE) / 8);
    cvt_k<4><<<(KV_C * NH * (K_NOPE + V_HD) / 8 + 255) / 256, 256>>>(w_ukv_w, KV_C * NH * (K_NOPE + V_HD) / 8);
    cvt_k<5><<<(NH * V_HD * DIM / 8 + 255) / 256, 256>>>(w_o_w, NH * V_HD * DIM / 8);

    // Q path
    hgemm_k<1, 0><<<dim3(Q_C / HBN, BSROWS / HBM), 128>>>(w_dq_b, (float*)0, Q_C, DIM);
    rmsnorm_q_k<<<BSROWS, 128>>>(q_norm_w);
    hgemm_k<3, 1><<<dim3(NH * QK_D / HBN, BSROWS / HBM), 128>>>(w_uq_qr_b, (float*)0, NH * QK_D, Q_C);
    rope_q_k<<<(BATCH * NH * S_LEN * (Q_ROPE / 2) + 255) / 256, 256>>>(pos, BATCH * NH * S_LEN * (Q_ROPE / 2));

    // KV path
    hgemm_k<2, 0><<<dim3((KV_C + K_ROPE) / HBN, BSROWS / HBM), 128>>>(w_dkv_b, (float*)0, KV_C + K_ROPE, DIM);
    kv_post_k<<<BSROWS, 128>>>(kv_norm_w, pos);
    hgemm_k<4, 2><<<dim3(NH * (K_NOPE + V_HD) / HBN, BSROWS / HBM), 128>>>(w_ukv_b, (float*)0, NH * (K_NOPE + V_HD), KV_C);

    // attention
    attn_h_k<<<dim3(S_LEN / AQT, NH, BATCH), 256>>>();

    // output projection
    hgemm_k<0, 3><<<dim3(DIM / HBN, BSROWS / HBM), 128>>>(w_o_b, out, DIM, NH * V_HD);
}

// round 10
// speedup vs baseline: 7.8042x; 1.3249x over previous
#include <cuda_runtime.h>
#include <cuda_fp16.h>
#include <cstdint>
#include <math.h>

typedef unsigned int u32;

// ---------------------------------------------------------------------------
// Problem constants
// ---------------------------------------------------------------------------
#define DIM     1024
#define NH      8
#define Q_C     128
#define Q_NOPE  96
#define Q_ROPE  32
#define KV_C    128
#define K_NOPE  64
#define K_ROPE  64
#define V_HD    256
#define S_LEN   2048
#define BATCH   2
#define BSROWS  (BATCH * S_LEN)       // 4096
#define QK_D    128
#define EPSV    1e-8f
#define SCALE   0.08838834764831845f  // 1/sqrt(128)

// ---------------------------------------------------------------------------
// Scratch (static device globals; no allocation allowed)
// ---------------------------------------------------------------------------
__device__ __half hx    [BSROWS * DIM];
__device__ __half hw_dq [DIM * Q_C];
__device__ __half hw_uq [Q_C * (NH * QK_D)];
__device__ __half hw_dkv[DIM * (KV_C + K_ROPE)];
__device__ __half hw_ukv[KV_C * (NH * (K_NOPE + V_HD))];
__device__ __half hw_o  [(NH * V_HD) * DIM];

__device__ float  g_cq_raw[BSROWS * Q_C];
__device__ __half g_cq_h  [BSROWS * Q_C];
__device__ float  g_ckvkr [BSROWS * (KV_C + K_ROPE)];
__device__ __half g_ckv_h [BSROWS * KV_C];
__device__ __half g_qs    [BATCH * NH * S_LEN * QK_D];   // scaled q, [B,H,S,128]
__device__ __half g_ks    [BATCH * NH * S_LEN * QK_D];
__device__ __half g_vs    [BATCH * NH * S_LEN * V_HD];
__device__ __half g_attn_h[BSROWS * (NH * V_HD)];

// ---------------------------------------------------------------------------
// PTX helpers
// ---------------------------------------------------------------------------
__device__ __forceinline__ u32 smem_a(const void* p) {
    return (u32)__cvta_generic_to_shared(p);
}
__device__ __forceinline__ void ldsm4(u32* r, u32 a) {
    asm volatile("ldmatrix.sync.aligned.m8n8.x4.shared.b16 {%0,%1,%2,%3},[%4];"
                 : "=r"(r[0]), "=r"(r[1]), "=r"(r[2]), "=r"(r[3]) : "r"(a));
}
__device__ __forceinline__ void ldsm4t(u32* r, u32 a) {
    asm volatile("ldmatrix.sync.aligned.m8n8.x4.trans.shared.b16 {%0,%1,%2,%3},[%4];"
                 : "=r"(r[0]), "=r"(r[1]), "=r"(r[2]), "=r"(r[3]) : "r"(a));
}
__device__ __forceinline__ void mma16816(float* d, const u32* a, const u32* b) {
    asm volatile("mma.sync.aligned.m16n8k16.row.col.f32.f16.f16.f32 "
                 "{%0,%1,%2,%3},{%4,%5,%6,%7},{%8,%9},{%0,%1,%2,%3};"
                 : "+f"(d[0]), "+f"(d[1]), "+f"(d[2]), "+f"(d[3])
                 : "r"(a[0]), "r"(a[1]), "r"(a[2]), "r"(a[3]), "r"(b[0]), "r"(b[1]));
}
__device__ __forceinline__ void cp_async16(u32 s, const void* g) {
    asm volatile("cp.async.cg.shared.global [%0], [%1], 16;" :: "r"(s), "l"(g));
}
__device__ __forceinline__ void cp_commit() {
    asm volatile("cp.async.commit_group;");
}
template <int N>
__device__ __forceinline__ void cp_wait() {
    asm volatile("cp.async.wait_group %0;" :: "n"(N));
}

// ---------------------------------------------------------------------------
// fp32 -> fp16 conversion (templated destination)
// ---------------------------------------------------------------------------
template <int DST>
__global__ void cvt_k(const float* __restrict__ src, int n8)
{
    __half* dst = DST == 0 ? hx : DST == 1 ? hw_dq : DST == 2 ? hw_uq :
                  DST == 3 ? hw_dkv : DST == 4 ? hw_ukv : hw_o;
    int i = blockIdx.x * blockDim.x + threadIdx.x;
    if (i >= n8) return;
    float4 f0 = ((const float4*)src)[2 * i];
    float4 f1 = ((const float4*)src)[2 * i + 1];
    union { __half2 h[4]; int4 v; } u;
    u.h[0] = __floats2half2_rn(f0.x, f0.y);
    u.h[1] = __floats2half2_rn(f0.z, f0.w);
    u.h[2] = __floats2half2_rn(f1.x, f1.y);
    u.h[3] = __floats2half2_rn(f1.z, f1.w);
    ((int4*)dst)[i] = u.v;
}

// ---------------------------------------------------------------------------
// Epilogue store
// EPI: 0=out fp32, 1=g_cq_raw, 2=g_ckvkr, 3=Q scatter(scaled,half), 4=KV scatter(half)
// ---------------------------------------------------------------------------
template <int EPI>
__device__ __forceinline__ void epi_store(int m, int n, float v, float* C, int N)
{
    int b = m / S_LEN, s = m - b * S_LEN;
    if (EPI == 0) {
        C[(size_t)m * N + n] = v;
    } else if (EPI == 1) {
        g_cq_raw[m * Q_C + n] = v;
    } else if (EPI == 2) {
        g_ckvkr[m * (KV_C + K_ROPE) + n] = v;
    } else if (EPI == 3) {
        int h, d;
        if (n < NH * Q_NOPE) { h = n / Q_NOPE; d = n % Q_NOPE; }
        else { int j = n - NH * Q_NOPE; h = j / Q_ROPE; d = Q_NOPE + (j % Q_ROPE); }
        g_qs[(((size_t)b * NH + h) * S_LEN + s) * QK_D + d] = __float2half(v * SCALE);
    } else {
        if (n < NH * K_NOPE) {
            int h = n / K_NOPE, d = n % K_NOPE;
            g_ks[(((size_t)b * NH + h) * S_LEN + s) * QK_D + d] = __float2half(v);
        } else {
            int j = n - NH * K_NOPE;
            int h = j / V_HD, d = j % V_HD;
            g_vs[(((size_t)b * NH + h) * S_LEN + s) * V_HD + d] = __float2half(v);
        }
    }
}

// ---------------------------------------------------------------------------
// HGEMM: 128x64x32 tile, 256 threads (8 warps 4x2), warp tile 32x32, fp16 mma.
// ---------------------------------------------------------------------------
#define HBM 128
#define HBN 64
#define HBK 32
#define ALD 40   // halfs: 80B stride -> conflict-free ldmatrix
#define BLD 72   // halfs: 144B stride

template <int EPI, int ASRC>
__global__ void __launch_bounds__(256) hgemm_k(const float* __restrict__ bias,
                                               float* __restrict__ C, int N, int K)
{
    const __half* A = ASRC == 0 ? hx : ASRC == 1 ? g_cq_h : ASRC == 2 ? g_ckv_h : g_attn_h;
    const __half* B = EPI == 1 ? hw_dq : EPI == 3 ? hw_uq : EPI == 2 ? hw_dkv :
                      EPI == 4 ? hw_ukv : hw_o;

    __shared__ __half sA[HBM * ALD];
    __shared__ __half sB[HBK * BLD];

    int tid = threadIdx.x, warp = tid >> 5, lane = tid & 31;
    int m0 = blockIdx.y * HBM, n0 = blockIdx.x * HBN;
    int wm = (warp >> 1) * 32, wn = (warp & 1) * 32;

    float acc[2][4][4];
#pragma unroll
    for (int i = 0; i < 2; i++)
#pragma unroll
        for (int j = 0; j < 4; j++)
#pragma unroll
            for (int k = 0; k < 4; k++) acc[i][j][k] = 0.f;

    int ar = tid >> 2, ac = (tid & 3) * 8;   // rows 0..63, two loads cover 128
    int br = tid >> 3, bc = (tid & 7) * 8;   // rows 0..31

    int4 av0 = *(const int4*)&A[(size_t)(m0 + ar) * K + ac];
    int4 av1 = *(const int4*)&A[(size_t)(m0 + 64 + ar) * K + ac];
    int4 bv0 = *(const int4*)&B[(size_t)br * N + n0 + bc];

    for (int k0 = 0; k0 < K; k0 += HBK) {
        __syncthreads();
        *(int4*)&sA[ar * ALD + ac] = av0;
        *(int4*)&sA[(64 + ar) * ALD + ac] = av1;
        *(int4*)&sB[br * BLD + bc] = bv0;
        __syncthreads();
        int kn = k0 + HBK;
        if (kn < K) {
            av0 = *(const int4*)&A[(size_t)(m0 + ar) * K + kn + ac];
            av1 = *(const int4*)&A[(size_t)(m0 + 64 + ar) * K + kn + ac];
            bv0 = *(const int4*)&B[(size_t)(kn + br) * N + n0 + bc];
        }
#pragma unroll
        for (int ks = 0; ks < 2; ks++) {
            u32 a[2][4], bm[4][2];
#pragma unroll
            for (int mi = 0; mi < 2; mi++)
                ldsm4(a[mi], smem_a(&sA[(wm + mi * 16 + (lane & 15)) * ALD + ks * 16 + (lane >> 4) * 8]));
#pragma unroll
            for (int njp = 0; njp < 2; njp++) {
                u32 r[4];
                ldsm4t(r, smem_a(&sB[(ks * 16 + ((lane >> 3) & 1) * 8 + (lane & 7)) * BLD
                                     + wn + njp * 16 + (lane >> 4) * 8]));
                bm[njp * 2][0] = r[0]; bm[njp * 2][1] = r[1];
                bm[njp * 2 + 1][0] = r[2]; bm[njp * 2 + 1][1] = r[3];
            }
#pragma unroll
            for (int mi = 0; mi < 2; mi++)
#pragma unroll
                for (int nj = 0; nj < 4; nj++)
                    mma16816(acc[mi][nj], a[mi], bm[nj]);
        }
    }

#pragma unroll
    for (int mi = 0; mi < 2; mi++)
#pragma unroll
        for (int nj = 0; nj < 4; nj++) {
            int row = m0 + wm + mi * 16 + (lane >> 2);
            int col = n0 + wn + nj * 8 + 2 * (lane & 3);
            epi_store<EPI>(row,     col,     acc[mi][nj][0] + bias[col],     C, N);
            epi_store<EPI>(row,     col + 1, acc[mi][nj][1] + bias[col + 1], C, N);
            epi_store<EPI>(row + 8, col,     acc[mi][nj][2] + bias[col],     C, N);
            epi_store<EPI>(row + 8, col + 1, acc[mi][nj][3] + bias[col + 1], C, N);
        }
}

// ---------------------------------------------------------------------------
// RMSNorm q: fp32 in -> half out
// ---------------------------------------------------------------------------
__global__ void rmsnorm_q_k(const float* __restrict__ w)
{
    int row = blockIdx.x, t = threadIdx.x;
    float v = g_cq_raw[row * Q_C + t];
    float ss = v * v;
#pragma unroll
    for (int off = 16; off > 0; off >>= 1) ss += __shfl_xor_sync(0xffffffffu, ss, off);
    __shared__ float s4[4];
    if ((t & 31) == 0) s4[t >> 5] = ss;
    __syncthreads();
    float tot = s4[0] + s4[1] + s4[2] + s4[3];
    float r = rsqrtf(tot * (1.0f / Q_C) + EPSV);
    g_cq_h[row * Q_C + t] = __float2half(w[t] * v * r);
}

// ---------------------------------------------------------------------------
// KV post: RMSNorm ckv -> half; RoPE k_rope -> broadcast (half) to all heads.
// ---------------------------------------------------------------------------
__global__ void kv_post_k(const float* __restrict__ kvw, const int* __restrict__ pos_ids)
{
    int row = blockIdx.x, t = threadIdx.x;
    const float* src = &g_ckvkr[row * (KV_C + K_ROPE)];
    float v = src[t];
    float ss = v * v;
#pragma unroll
    for (int off = 16; off > 0; off >>= 1) ss += __shfl_xor_sync(0xffffffffu, ss, off);
    __shared__ float s4[4];
    if ((t & 31) == 0) s4[t >> 5] = ss;
    __syncthreads();
    float tot = s4[0] + s4[1] + s4[2] + s4[3];
    float r = rsqrtf(tot * (1.0f / KV_C) + EPSV);
    g_ckv_h[row * KV_C + t] = __float2half(kvw[t] * v * r);

    if (t < K_ROPE / 2) {
        int i = t;
        float xe = src[KV_C + 2 * i];
        float xo = src[KV_C + 2 * i + 1];
        float p = (float)pos_ids[row];
        float inv = expf(-((float)(2 * i) / (float)K_ROPE) * 9.210340371976184f);
        float sn, cs;
        sincosf(p * inv, &sn, &cs);
        __half re = __float2half(xe * cs - xo * sn);
        __half ro = __float2half(xe * sn + xo * cs);
        int b = row / S_LEN, s = row - b * S_LEN;
#pragma unroll
        for (int h = 0; h < NH; h++) {
            size_t base = (((size_t)b * NH + h) * S_LEN + s) * QK_D + K_NOPE;
            g_ks[base + 2 * i]     = re;
            g_ks[base + 2 * i + 1] = ro;
        }
    }
}

// ---------------------------------------------------------------------------
// RoPE on Q rope half (dims 96..127), half in-place. (Q already scaled.)
// ---------------------------------------------------------------------------
__global__ void rope_q_k(const int* __restrict__ pos_ids, int total)
{
    int idx = blockIdx.x * blockDim.x + threadIdx.x;
    if (idx >= total) return;
    int i = idx & 15;
    int bhs = idx >> 4;
    int s = bhs % S_LEN;
    int bh = bhs / S_LEN;
    int b = bh / NH;
    float p = (float)pos_ids[b * S_LEN + s];
    float inv = expf(-((float)(2 * i) / (float)Q_ROPE) * 9.210340371976184f);
    float sn, cs;
    sincosf(p * inv, &sn, &cs);
    size_t base = (size_t)bhs * QK_D + Q_NOPE;
    float xe = __half2float(g_qs[base + 2 * i]);
    float xo = __half2float(g_qs[base + 2 * i + 1]);
    g_qs[base + 2 * i]     = __float2half(xe * cs - xo * sn);
    g_qs[base + 2 * i + 1] = __float2half(xe * sn + xo * cs);
}

// ---------------------------------------------------------------------------
// Flash attention, fp16 mma. Grid (32, 8, 2), 128 threads = 4 warps.
// Each warp owns 16 query rows x full 256-d output. Scores computed ONCE.
// Q fragments preloaded to registers; K/V double-buffered via cp.async in
// dynamic smem (2 stages x 32 keys).
// ---------------------------------------------------------------------------
#define AQT 64
#define ACH 32
#define QLD 136
#define KLD 136
#define VLD 264
// dynamic smem: K stages then V stages
#define SM_K_BYTES (2 * ACH * KLD * 2)      // 17408
#define SM_V_BYTES (2 * ACH * VLD * 2)      // 33792
#define SMEM_ATT   (SM_K_BYTES + SM_V_BYTES) // 51200

__global__ void __launch_bounds__(128) attn_h_k()
{
    extern __shared__ __half dsm[];
    __half* sK = dsm;                        // [2][ACH][KLD]
    __half* sV = dsm + 2 * ACH * KLD;        // [2][ACH][VLD]

    int tid = threadIdx.x, warp = tid >> 5, lane = tid & 31;
    int qt = blockIdx.x, h = blockIdx.y, b = blockIdx.z;

    const __half* Qg = g_qs + (((size_t)b * NH + h) * S_LEN + (size_t)qt * AQT) * QK_D;
    const __half* Kg = g_ks + ((size_t)b * NH + h) * S_LEN * QK_D;
    const __half* Vg = g_vs + ((size_t)b * NH + h) * S_LEN * V_HD;

    // ---- stage Q through (reused) K smem region, preload A-fragments ----
    {
        __half* qbuf = sK;                   // 64*QLD*2 = 17408 bytes, fits exactly
#pragma unroll
        for (int r = 0; r < 8; r++) {
            int idx = r * 128 + tid, row = idx >> 4, c = (idx & 15) * 8;
            *(int4*)&qbuf[row * QLD + c] = *(const int4*)&Qg[row * QK_D + c];
        }
    }
    __syncthreads();
    u32 qa[8][4];
#pragma unroll
    for (int ks = 0; ks < 8; ks++)
        ldsm4(qa[ks], smem_a(&sK[(warp * 16 + (lane & 15)) * QLD + ks * 16 + (lane >> 4) * 8]));
    __syncthreads();   // everyone done reading qbuf before cp.async overwrites

    float m_i[2] = { -1e30f, -1e30f }, l_i[2] = { 0.f, 0.f };
    float o[32][4];
#pragma unroll
    for (int nt = 0; nt < 32; nt++)
#pragma unroll
        for (int j = 0; j < 4; j++) o[nt][j] = 0.f;

    u32 sK_a = smem_a(sK), sV_a = smem_a(sV);

    // ---- issue stage 0 ----
    {
        const __half* Kn = Kg;
        const __half* Vn = Vg;
#pragma unroll
        for (int r = 0; r < 4; r++) {
            int idx = r * 128 + tid, row = idx >> 4, c = (idx & 15) * 8;
            cp_async16(sK_a + (row * KLD + c) * 2, &Kn[(size_t)row * QK_D + c]);
        }
#pragma unroll
        for (int r = 0; r < 8; r++) {
            int idx = r * 128 + tid, row = idx >> 5, c = (idx & 31) * 8;
            cp_async16(sV_a + (row * VLD + c) * 2, &Vn[(size_t)row * V_HD + c]);
        }
        cp_commit();
    }

    const int NCH = S_LEN / ACH;
    for (int kc = 0; kc < NCH; kc++) {
        int buf = kc & 1;
        if (kc + 1 < NCH) {
            int nbuf = (kc + 1) & 1;
            const __half* Kn = Kg + (size_t)(kc + 1) * ACH * QK_D;
            const __half* Vn = Vg + (size_t)(kc + 1) * ACH * V_HD;
#pragma unroll
            for (int r = 0; r < 4; r++) {
                int idx = r * 128 + tid, row = idx >> 4, c = (idx & 15) * 8;
                cp_async16(sK_a + ((nbuf * ACH + row) * KLD + c) * 2, &Kn[(size_t)row * QK_D + c]);
            }
#pragma unroll
            for (int r = 0; r < 8; r++) {
                int idx = r * 128 + tid, row = idx >> 5, c = (idx & 31) * 8;
                cp_async16(sV_a + ((nbuf * ACH + row) * VLD + c) * 2, &Vn[(size_t)row * V_HD + c]);
            }
            cp_commit();
            cp_wait<1>();
        } else {
            cp_wait<0>();
        }
        __syncthreads();

        const __half* sKb = sK + buf * ACH * KLD;
        const __half* sVb = sV + buf * ACH * VLD;

        // ---- scores S = Q K^T (pre-scaled Q) ----
        float sc[4][4];
#pragma unroll
        for (int nj = 0; nj < 4; nj++)
#pragma unroll
            for (int j = 0; j < 4; j++) sc[nj][j] = 0.f;

#pragma unroll
        for (int ks = 0; ks < 8; ks++) {
            u32 bm[4][2];
#pragma unroll
            for (int njp = 0; njp < 2; njp++) {
                u32 r[4];
                ldsm4(r, smem_a(&sKb[(njp * 16 + ((lane >> 4) & 1) * 8 + (lane & 7)) * KLD
                                     + ks * 16 + ((lane >> 3) & 1) * 8]));
                bm[njp * 2][0] = r[0]; bm[njp * 2][1] = r[1];
                bm[njp * 2 + 1][0] = r[2]; bm[njp * 2 + 1][1] = r[3];
            }
#pragma unroll
            for (int nj = 0; nj < 4; nj++) mma16816(sc[nj], qa[ks], bm[nj]);
        }

        // ---- online softmax ----
        u32 p2[2][4];
#pragma unroll
        for (int i = 0; i < 2; i++) {
            float mx = -1e30f;
#pragma unroll
            for (int nj = 0; nj < 4; nj++)
                mx = fmaxf(mx, fmaxf(sc[nj][2 * i], sc[nj][2 * i + 1]));
            mx = fmaxf(mx, __shfl_xor_sync(0xffffffffu, mx, 1));
            mx = fmaxf(mx, __shfl_xor_sync(0xffffffffu, mx, 2));
            float mn = fmaxf(m_i[i], mx);
            float rs = 0.f;
#pragma unroll
            for (int nj = 0; nj < 4; nj++) {
                float p0 = __expf(sc[nj][2 * i] - mn);
                float p1 = __expf(sc[nj][2 * i + 1] - mn);
                rs += p0 + p1;
                __half2 hh = __floats2half2_rn(p0, p1);
                p2[i][nj] = *(u32*)&hh;
            }
            rs += __shfl_xor_sync(0xffffffffu, rs, 1);
            rs += __shfl_xor_sync(0xffffffffu, rs, 2);
            float corr = __expf(m_i[i] - mn);
            l_i[i] = l_i[i] * corr + rs;
            m_i[i] = mn;
#pragma unroll
            for (int nt = 0; nt < 32; nt++) {
                o[nt][2 * i] *= corr; o[nt][2 * i + 1] *= corr;
            }
        }

        // ---- O += P V (full 256-d per warp) ----
#pragma unroll
        for (int kt = 0; kt < 2; kt++) {
            u32 a[4] = { p2[0][2 * kt], p2[1][2 * kt], p2[0][2 * kt + 1], p2[1][2 * kt + 1] };
#pragma unroll
            for (int njp = 0; njp < 16; njp++) {
                u32 r[4];
                ldsm4t(r, smem_a(&sVb[(kt * 16 + ((lane >> 3) & 1) * 8 + (lane & 7)) * VLD
                                      + njp * 16 + (lane >> 4) * 8]));
                u32 b0[2] = { r[0], r[1] }, b1[2] = { r[2], r[3] };
                mma16816(o[njp * 2], a, b0);
                mma16816(o[njp * 2 + 1], a, b1);
            }
        }

        __syncthreads();  // compute done before next prefetch overwrites this buf
    }

    // ---- epilogue ----
#pragma unroll
    for (int i = 0; i < 2; i++) {
        float inv = 1.f / l_i[i];
        int row = qt * AQT + warp * 16 + (lane >> 2) + i * 8;
        size_t base = ((size_t)b * S_LEN + row) * (NH * V_HD) + h * V_HD;
#pragma unroll
        for (int nt = 0; nt < 32; nt++) {
            __half2 hh = __floats2half2_rn(o[nt][2 * i] * inv, o[nt][2 * i + 1] * inv);
            *(__half2*)&g_attn_h[base + nt * 8 + 2 * (lane & 3)] = hh;
        }
    }
}

// ---------------------------------------------------------------------------
// Launch
// ---------------------------------------------------------------------------
extern "C" void kernel_launch(void* const* d_in, const int* in_sizes, int n_in,
                              void* d_out, int out_size)
{
    const float* x         = (const float*)d_in[0];
    const int*   pos       = (const int*)  d_in[1];
    const float* w_dq_w    = (const float*)d_in[2];
    const float* w_dq_b    = (const float*)d_in[3];
    const float* q_norm_w  = (const float*)d_in[4];
    const float* w_uq_qr_w = (const float*)d_in[5];
    const float* w_uq_qr_b = (const float*)d_in[6];
    const float* w_dkv_w   = (const float*)d_in[7];
    const float* w_dkv_b   = (const float*)d_in[8];
    const float* kv_norm_w = (const float*)d_in[9];
    const float* w_ukv_w   = (const float*)d_in[10];
    const float* w_ukv_b   = (const float*)d_in[11];
    const float* w_o_w     = (const float*)d_in[12];
    const float* w_o_b     = (const float*)d_in[13];
    float* out = (float*)d_out;

    static int smem_set = 0;
    if (!smem_set) {
        cudaFuncSetAttribute(attn_h_k, cudaFuncAttributeMaxDynamicSharedMemorySize, SMEM_ATT);
        smem_set = 1;
    }

    // fp32 -> fp16 conversions
    cvt_k<0><<<(BSROWS * DIM / 8 + 255) / 256, 256>>>(x, BSROWS * DIM / 8);
    cvt_k<1><<<(DIM * Q_C / 8 + 255) / 256, 256>>>(w_dq_w, DIM * Q_C / 8);
    cvt_k<2><<<(Q_C * NH * QK_D / 8 + 255) / 256, 256>>>(w_uq_qr_w, Q_C * NH * QK_D / 8);
    cvt_k<3><<<(DIM * (KV_C + K_ROPE) / 8 + 255) / 256, 256>>>(w_dkv_w, DIM * (KV_C + K_ROPE) / 8);
    cvt_k<4><<<(KV_C * NH * (K_NOPE + V_HD) / 8 + 255) / 256, 256>>>(w_ukv_w, KV_C * NH * (K_NOPE + V_HD) / 8);
    cvt_k<5><<<(NH * V_HD * DIM / 8 + 255) / 256, 256>>>(w_o_w, NH * V_HD * DIM / 8);

    // Q path
    hgemm_k<1, 0><<<dim3(Q_C / HBN, BSROWS / HBM), 256>>>(w_dq_b, (float*)0, Q_C, DIM);
    rmsnorm_q_k<<<BSROWS, 128>>>(q_norm_w);
    hgemm_k<3, 1><<<dim3(NH * QK_D / HBN, BSROWS / HBM), 256>>>(w_uq_qr_b, (float*)0, NH * QK_D, Q_C);
    rope_q_k<<<(BATCH * NH * S_LEN * (Q_ROPE / 2) + 255) / 256, 256>>>(pos, BATCH * NH * S_LEN * (Q_ROPE / 2));

    // KV path
    hgemm_k<2, 0><<<dim3((KV_C + K_ROPE) / HBN, BSROWS / HBM), 256>>>(w_dkv_b, (float*)0, KV_C + K_ROPE, DIM);
    kv_post_k<<<BSROWS, 128>>>(kv_norm_w, pos);
    hgemm_k<4, 2><<<dim3(NH * (K_NOPE + V_HD) / HBN, BSROWS / HBM), 256>>>(w_ukv_b, (float*)0, NH * (K_NOPE + V_HD), KV_C);

    // attention
    attn_h_k<<<dim3(S_LEN / AQT, NH, BATCH), 128, SMEM_ATT>>>();

    // output projection
    hgemm_k<0, 3><<<dim3(DIM / HBN, BSROWS / HBM), 256>>>(w_o_b, out, DIM, NH * V_HD);
}

// round 11
// speedup vs baseline: 8.7449x; 1.1205x over previous
#include <cuda_runtime.h>
#include <cuda_fp16.h>
#include <cstdint>
#include <math.h>

typedef unsigned int u32;

// ---------------------------------------------------------------------------
// Problem constants
// ---------------------------------------------------------------------------
#define DIM     1024
#define NH      8
#define Q_C     128
#define Q_NOPE  96
#define Q_ROPE  32
#define KV_C    128
#define K_NOPE  64
#define K_ROPE  64
#define V_HD    256
#define S_LEN   2048
#define BATCH   2
#define BSROWS  (BATCH * S_LEN)       // 4096
#define QK_D    128
#define EPSV    1e-8f
// 1/sqrt(128) * log2(e)  (softmax runs in base-2 domain)
#define QSC     (0.08838834764831845f * 1.4426950408889634f)

// ---------------------------------------------------------------------------
// Scratch (static device globals; no allocation allowed)
// ---------------------------------------------------------------------------
__device__ __half hx    [BSROWS * DIM];
__device__ __half hw_dq [DIM * Q_C];
__device__ __half hw_uq [Q_C * (NH * QK_D)];
__device__ __half hw_dkv[DIM * (KV_C + K_ROPE)];
__device__ __half hw_ukv[KV_C * (NH * (K_NOPE + V_HD))];
__device__ __half hw_o  [(NH * V_HD) * DIM];

__device__ float  g_cq_raw[BSROWS * Q_C];
__device__ __half g_cq_h  [BSROWS * Q_C];
__device__ float  g_ckvkr [BSROWS * (KV_C + K_ROPE)];
__device__ __half g_ckv_h [BSROWS * KV_C];
__device__ __half g_qs    [BATCH * NH * S_LEN * QK_D];   // scaled+roped q
__device__ __half g_ks    [BATCH * NH * S_LEN * QK_D];
__device__ __half g_vs    [BATCH * NH * S_LEN * V_HD];
__device__ __half g_attn_h[BSROWS * (NH * V_HD)];

// ---------------------------------------------------------------------------
// PTX helpers
// ---------------------------------------------------------------------------
__device__ __forceinline__ u32 smem_a(const void* p) {
    return (u32)__cvta_generic_to_shared(p);
}
__device__ __forceinline__ void ldsm4(u32* r, u32 a) {
    asm volatile("ldmatrix.sync.aligned.m8n8.x4.shared.b16 {%0,%1,%2,%3},[%4];"
                 : "=r"(r[0]), "=r"(r[1]), "=r"(r[2]), "=r"(r[3]) : "r"(a));
}
__device__ __forceinline__ void ldsm4t(u32* r, u32 a) {
    asm volatile("ldmatrix.sync.aligned.m8n8.x4.trans.shared.b16 {%0,%1,%2,%3},[%4];"
                 : "=r"(r[0]), "=r"(r[1]), "=r"(r[2]), "=r"(r[3]) : "r"(a));
}
__device__ __forceinline__ void mma16816(float* d, const u32* a, const u32* b) {
    asm volatile("mma.sync.aligned.m16n8k16.row.col.f32.f16.f16.f32 "
                 "{%0,%1,%2,%3},{%4,%5,%6,%7},{%8,%9},{%0,%1,%2,%3};"
                 : "+f"(d[0]), "+f"(d[1]), "+f"(d[2]), "+f"(d[3])
                 : "r"(a[0]), "r"(a[1]), "r"(a[2]), "r"(a[3]), "r"(b[0]), "r"(b[1]));
}
__device__ __forceinline__ void cp_async16(u32 s, const void* g) {
    asm volatile("cp.async.cg.shared.global [%0], [%1], 16;" :: "r"(s), "l"(g));
}
__device__ __forceinline__ void cp_commit() {
    asm volatile("cp.async.commit_group;");
}
template <int N>
__device__ __forceinline__ void cp_wait() {
    asm volatile("cp.async.wait_group %0;" :: "n"(N));
}

// ---------------------------------------------------------------------------
// Merged fp32 -> fp16 conversion for x + all 5 weights (one launch)
// ---------------------------------------------------------------------------
#define CN0 (BSROWS * DIM / 8)                         // x      524288
#define CN1 (CN0 + DIM * Q_C / 8)                      // dq     +16384
#define CN2 (CN1 + Q_C * NH * QK_D / 8)                // uq     +16384
#define CN3 (CN2 + DIM * (KV_C + K_ROPE) / 8)          // dkv    +24576
#define CN4 (CN3 + KV_C * NH * (K_NOPE + V_HD) / 8)    // ukv    +40960
#define CN5 (CN4 + NH * V_HD * DIM / 8)                // o      +262144

__global__ void cvt_all_k(const float* __restrict__ x,   const float* __restrict__ dq,
                          const float* __restrict__ uq,  const float* __restrict__ dkv,
                          const float* __restrict__ ukv, const float* __restrict__ o)
{
    int i = blockIdx.x * blockDim.x + threadIdx.x;
    if (i >= CN5) return;
    const float* src; __half* dst; int off;
    if      (i < CN0) { src = x;   dst = hx;     off = i; }
    else if (i < CN1) { src = dq;  dst = hw_dq;  off = i - CN0; }
    else if (i < CN2) { src = uq;  dst = hw_uq;  off = i - CN1; }
    else if (i < CN3) { src = dkv; dst = hw_dkv; off = i - CN2; }
    else if (i < CN4) { src = ukv; dst = hw_ukv; off = i - CN3; }
    else              { src = o;   dst = hw_o;   off = i - CN4; }
    float4 f0 = ((const float4*)src)[2 * off];
    float4 f1 = ((const float4*)src)[2 * off + 1];
    union { __half2 h[4]; int4 v; } u;
    u.h[0] = __floats2half2_rn(f0.x, f0.y);
    u.h[1] = __floats2half2_rn(f0.z, f0.w);
    u.h[2] = __floats2half2_rn(f1.x, f1.y);
    u.h[3] = __floats2half2_rn(f1.z, f1.w);
    ((int4*)dst)[off] = u.v;
}

// ---------------------------------------------------------------------------
// Paired epilogue store (n even, pair (n, n+1))
// EPI: 0=out fp32, 1=g_cq_raw, 2=g_ckvkr, 3=Q scatter(scaled+roped), 4=KV scatter
// ---------------------------------------------------------------------------
template <int EPI>
__device__ __forceinline__ void epi_pair(int m, int n, float v0, float v1,
                                         float* C, int N, const int* pos)
{
    int b = m / S_LEN, s = m - b * S_LEN;
    if (EPI == 0) {
        *(float2*)&C[(size_t)m * N + n] = make_float2(v0, v1);
    } else if (EPI == 1) {
        *(float2*)&g_cq_raw[m * Q_C + n] = make_float2(v0, v1);
    } else if (EPI == 2) {
        *(float2*)&g_ckvkr[m * (KV_C + K_ROPE) + n] = make_float2(v0, v1);
    } else if (EPI == 3) {
        int h, d;
        if (n < NH * Q_NOPE) { h = n / Q_NOPE; d = n % Q_NOPE; }
        else { int j = n - NH * Q_NOPE; h = j / Q_ROPE; d = Q_NOPE + (j % Q_ROPE); }
        v0 *= QSC; v1 *= QSC;
        if (d >= Q_NOPE) {   // fused RoPE (pair is exactly (2i, 2i+1))
            float p = (float)pos[b * S_LEN + s];
            float inv = __expf(-((float)(d - Q_NOPE) / (float)Q_ROPE) * 9.210340371976184f);
            float sn, cs;
            __sincosf(p * inv, &sn, &cs);
            float r0 = v0 * cs - v1 * sn;
            float r1 = v0 * sn + v1 * cs;
            v0 = r0; v1 = r1;
        }
        *(__half2*)&g_qs[(((size_t)b * NH + h) * S_LEN + s) * QK_D + d] =
            __floats2half2_rn(v0, v1);
    } else {
        if (n < NH * K_NOPE) {
            int h = n / K_NOPE, d = n % K_NOPE;
            *(__half2*)&g_ks[(((size_t)b * NH + h) * S_LEN + s) * QK_D + d] =
                __floats2half2_rn(v0, v1);
        } else {
            int j = n - NH * K_NOPE;
            int h = j / V_HD, d = j % V_HD;
            *(__half2*)&g_vs[(((size_t)b * NH + h) * S_LEN + s) * V_HD + d] =
                __floats2half2_rn(v0, v1);
        }
    }
}

// ---------------------------------------------------------------------------
// HGEMM: 128x64x32 tile, 256 threads (8 warps 4x2), warp tile 32x32, fp16 mma.
// ---------------------------------------------------------------------------
#define HBM 128
#define HBN 64
#define HBK 32
#define ALD 40
#define BLD 72

template <int EPI, int ASRC>
__global__ void __launch_bounds__(256) hgemm_k(const float* __restrict__ bias,
                                               float* __restrict__ C, int N, int K,
                                               const int* __restrict__ pos)
{
    const __half* A = ASRC == 0 ? hx : ASRC == 1 ? g_cq_h : ASRC == 2 ? g_ckv_h : g_attn_h;
    const __half* B = EPI == 1 ? hw_dq : EPI == 3 ? hw_uq : EPI == 2 ? hw_dkv :
                      EPI == 4 ? hw_ukv : hw_o;

    __shared__ __half sA[HBM * ALD];
    __shared__ __half sB[HBK * BLD];

    int tid = threadIdx.x, warp = tid >> 5, lane = tid & 31;
    int m0 = blockIdx.y * HBM, n0 = blockIdx.x * HBN;
    int wm = (warp >> 1) * 32, wn = (warp & 1) * 32;

    float acc[2][4][4];
#pragma unroll
    for (int i = 0; i < 2; i++)
#pragma unroll
        for (int j = 0; j < 4; j++)
#pragma unroll
            for (int k = 0; k < 4; k++) acc[i][j][k] = 0.f;

    int ar = tid >> 2, ac = (tid & 3) * 8;
    int br = tid >> 3, bc = (tid & 7) * 8;

    int4 av0 = *(const int4*)&A[(size_t)(m0 + ar) * K + ac];
    int4 av1 = *(const int4*)&A[(size_t)(m0 + 64 + ar) * K + ac];
    int4 bv0 = *(const int4*)&B[(size_t)br * N + n0 + bc];

    for (int k0 = 0; k0 < K; k0 += HBK) {
        __syncthreads();
        *(int4*)&sA[ar * ALD + ac] = av0;
        *(int4*)&sA[(64 + ar) * ALD + ac] = av1;
        *(int4*)&sB[br * BLD + bc] = bv0;
        __syncthreads();
        int kn = k0 + HBK;
        if (kn < K) {
            av0 = *(const int4*)&A[(size_t)(m0 + ar) * K + kn + ac];
            av1 = *(const int4*)&A[(size_t)(m0 + 64 + ar) * K + kn + ac];
            bv0 = *(const int4*)&B[(size_t)(kn + br) * N + n0 + bc];
        }
#pragma unroll
        for (int ks = 0; ks < 2; ks++) {
            u32 a[2][4], bm[4][2];
#pragma unroll
            for (int mi = 0; mi < 2; mi++)
                ldsm4(a[mi], smem_a(&sA[(wm + mi * 16 + (lane & 15)) * ALD + ks * 16 + (lane >> 4) * 8]));
#pragma unroll
            for (int njp = 0; njp < 2; njp++) {
                u32 r[4];
                ldsm4t(r, smem_a(&sB[(ks * 16 + ((lane >> 3) & 1) * 8 + (lane & 7)) * BLD
                                     + wn + njp * 16 + (lane >> 4) * 8]));
                bm[njp * 2][0] = r[0]; bm[njp * 2][1] = r[1];
                bm[njp * 2 + 1][0] = r[2]; bm[njp * 2 + 1][1] = r[3];
            }
#pragma unroll
            for (int mi = 0; mi < 2; mi++)
#pragma unroll
                for (int nj = 0; nj < 4; nj++)
                    mma16816(acc[mi][nj], a[mi], bm[nj]);
        }
    }

#pragma unroll
    for (int mi = 0; mi < 2; mi++)
#pragma unroll
        for (int nj = 0; nj < 4; nj++) {
            int row = m0 + wm + mi * 16 + (lane >> 2);
            int col = n0 + wn + nj * 8 + 2 * (lane & 3);
            float b0 = bias[col], b1 = bias[col + 1];
            epi_pair<EPI>(row,     col, acc[mi][nj][0] + b0, acc[mi][nj][1] + b1, C, N, pos);
            epi_pair<EPI>(row + 8, col, acc[mi][nj][2] + b0, acc[mi][nj][3] + b1, C, N, pos);
        }
}

// ---------------------------------------------------------------------------
// RMSNorm q: fp32 in -> half out
// ---------------------------------------------------------------------------
__global__ void rmsnorm_q_k(const float* __restrict__ w)
{
    int row = blockIdx.x, t = threadIdx.x;
    float v = g_cq_raw[row * Q_C + t];
    float ss = v * v;
#pragma unroll
    for (int off = 16; off > 0; off >>= 1) ss += __shfl_xor_sync(0xffffffffu, ss, off);
    __shared__ float s4[4];
    if ((t & 31) == 0) s4[t >> 5] = ss;
    __syncthreads();
    float tot = s4[0] + s4[1] + s4[2] + s4[3];
    float r = rsqrtf(tot * (1.0f / Q_C) + EPSV);
    g_cq_h[row * Q_C + t] = __float2half(w[t] * v * r);
}

// ---------------------------------------------------------------------------
// KV post: RMSNorm ckv -> half; RoPE k_rope -> broadcast (half) to all heads.
// ---------------------------------------------------------------------------
__global__ void kv_post_k(const float* __restrict__ kvw, const int* __restrict__ pos_ids)
{
    int row = blockIdx.x, t = threadIdx.x;
    const float* src = &g_ckvkr[row * (KV_C + K_ROPE)];
    float v = src[t];
    float ss = v * v;
#pragma unroll
    for (int off = 16; off > 0; off >>= 1) ss += __shfl_xor_sync(0xffffffffu, ss, off);
    __shared__ float s4[4];
    if ((t & 31) == 0) s4[t >> 5] = ss;
    __syncthreads();
    float tot = s4[0] + s4[1] + s4[2] + s4[3];
    float r = rsqrtf(tot * (1.0f / KV_C) + EPSV);
    g_ckv_h[row * KV_C + t] = __float2half(kvw[t] * v * r);

    if (t < K_ROPE / 2) {
        int i = t;
        float xe = src[KV_C + 2 * i];
        float xo = src[KV_C + 2 * i + 1];
        float p = (float)pos_ids[row];
        float inv = expf(-((float)(2 * i) / (float)K_ROPE) * 9.210340371976184f);
        float sn, cs;
        sincosf(p * inv, &sn, &cs);
        __half re = __float2half(xe * cs - xo * sn);
        __half ro = __float2half(xe * sn + xo * cs);
        int b = row / S_LEN, s = row - b * S_LEN;
#pragma unroll
        for (int h = 0; h < NH; h++) {
            size_t base = (((size_t)b * NH + h) * S_LEN + s) * QK_D + K_NOPE;
            g_ks[base + 2 * i]     = re;
            g_ks[base + 2 * i + 1] = ro;
        }
    }
}

// ---------------------------------------------------------------------------
// Flash attention, fp16 mma, base-2 softmax. Grid (32, 8, 2), 128 thr = 4 warps.
// Each warp: 16 query rows x full 256-d output. 64-key chunks.
// Q resident in smem (re-ldmatrix'd per chunk); K double-buffered cp.async;
// V single-buffered (latency hides behind scores+softmax). Commit order V-then-K
// with wait_group<1> guarantees V(kc)+K(kc) complete at top of chunk kc.
// ---------------------------------------------------------------------------
#define AQT 64
#define ACH 64
#define QLD 136
#define KLD 136
#define VLD 264
#define SM_Q (AQT * QLD)            // halfs
#define SM_K (2 * ACH * KLD)
#define SM_V (ACH * VLD)
#define SMEM_ATT ((SM_Q + SM_K + SM_V) * 2)   // 86016 bytes

__global__ void __launch_bounds__(128) attn_h_k()
{
    extern __shared__ __half dsm[];
    __half* sQ = dsm;                 // [AQT][QLD]
    __half* sK = dsm + SM_Q;          // [2][ACH][KLD]
    __half* sV = dsm + SM_Q + SM_K;   // [ACH][VLD]

    int tid = threadIdx.x, warp = tid >> 5, lane = tid & 31;
    int qt = blockIdx.x, h = blockIdx.y, b = blockIdx.z;

    const __half* Qg = g_qs + (((size_t)b * NH + h) * S_LEN + (size_t)qt * AQT) * QK_D;
    const __half* Kg = g_ks + ((size_t)b * NH + h) * S_LEN * QK_D;
    const __half* Vg = g_vs + ((size_t)b * NH + h) * S_LEN * V_HD;

    u32 sK_a = smem_a(sK), sV_a = smem_a(sV);

    // ---- prologue: K0 group, V0 group, K1 group (commit order matters) ----
#pragma unroll
    for (int r = 0; r < 8; r++) {
        int idx = r * 128 + tid, row = idx >> 4, c = (idx & 15) * 8;
        cp_async16(sK_a + (row * KLD + c) * 2, &Kg[(size_t)row * QK_D + c]);
    }
    cp_commit();
#pragma unroll
    for (int r = 0; r < 16; r++) {
        int idx = r * 128 + tid, row = idx >> 5, c = (idx & 31) * 8;
        cp_async16(sV_a + (row * VLD + c) * 2, &Vg[(size_t)row * V_HD + c]);
    }
    cp_commit();
#pragma unroll
    for (int r = 0; r < 8; r++) {
        int idx = r * 128 + tid, row = idx >> 4, c = (idx & 15) * 8;
        cp_async16(sK_a + ((ACH + row) * KLD + c) * 2, &Kg[(size_t)(ACH + row) * QK_D + c]);
    }
    cp_commit();

    // ---- stage Q (plain stores; visibility via first in-loop barrier) ----
#pragma unroll
    for (int r = 0; r < 8; r++) {
        int idx = r * 128 + tid, row = idx >> 4, c = (idx & 15) * 8;
        *(int4*)&sQ[row * QLD + c] = *(const int4*)&Qg[row * QK_D + c];
    }

    float m_i[2] = { -1e30f, -1e30f }, l_i[2] = { 0.f, 0.f };
    float o[32][4];
#pragma unroll
    for (int nt = 0; nt < 32; nt++)
#pragma unroll
        for (int j = 0; j < 4; j++) o[nt][j] = 0.f;

    const int NCH = S_LEN / ACH;    // 32
    for (int kc = 0; kc < NCH; kc++) {
        int buf = kc & 1;
        cp_wait<1>();          // K(kc) and V(kc) complete (only K(kc+1) pending)
        __syncthreads();

        const __half* sKb = sK + buf * ACH * KLD;

        // ---- scores S = Q K^T (Q pre-scaled by 1/sqrt(d)*log2e) ----
        float sc[8][4];
#pragma unroll
        for (int nj = 0; nj < 8; nj++)
#pragma unroll
            for (int j = 0; j < 4; j++) sc[nj][j] = 0.f;

#pragma unroll
        for (int ks = 0; ks < 8; ks++) {
            u32 qa[4];
            ldsm4(qa, smem_a(&sQ[(warp * 16 + (lane & 15)) * QLD + ks * 16 + (lane >> 4) * 8]));
            u32 bm[8][2];
#pragma unroll
            for (int njp = 0; njp < 4; njp++) {
                u32 r[4];
                ldsm4(r, smem_a(&sKb[(njp * 16 + ((lane >> 4) & 1) * 8 + (lane & 7)) * KLD
                                     + ks * 16 + ((lane >> 3) & 1) * 8]));
                bm[njp * 2][0] = r[0]; bm[njp * 2][1] = r[1];
                bm[njp * 2 + 1][0] = r[2]; bm[njp * 2 + 1][1] = r[3];
            }
#pragma unroll
            for (int nj = 0; nj < 8; nj++) mma16816(sc[nj], qa, bm[nj]);
        }

        // ---- online softmax (base 2) ----
        u32 p2[2][8];
#pragma unroll
        for (int i = 0; i < 2; i++) {
            float mx = -1e30f;
#pragma unroll
            for (int nj = 0; nj < 8; nj++)
                mx = fmaxf(mx, fmaxf(sc[nj][2 * i], sc[nj][2 * i + 1]));
            mx = fmaxf(mx, __shfl_xor_sync(0xffffffffu, mx, 1));
            mx = fmaxf(mx, __shfl_xor_sync(0xffffffffu, mx, 2));
            float mn = fmaxf(m_i[i], mx);
            float rs = 0.f;
#pragma unroll
            for (int nj = 0; nj < 8; nj++) {
                float p0 = exp2f(sc[nj][2 * i] - mn);
                float p1 = exp2f(sc[nj][2 * i + 1] - mn);
                rs += p0 + p1;
                __half2 hh = __floats2half2_rn(p0, p1);
                p2[i][nj] = *(u32*)&hh;
            }
            rs += __shfl_xor_sync(0xffffffffu, rs, 1);
            rs += __shfl_xor_sync(0xffffffffu, rs, 2);
            float corr = exp2f(m_i[i] - mn);
            l_i[i] = l_i[i] * corr + rs;
            m_i[i] = mn;
#pragma unroll
            for (int nt = 0; nt < 32; nt++) {
                o[nt][2 * i] *= corr; o[nt][2 * i + 1] *= corr;
            }
        }

        // ---- O += P V ----
#pragma unroll
        for (int kt = 0; kt < 4; kt++) {
            u32 a[4] = { p2[0][2 * kt], p2[1][2 * kt], p2[0][2 * kt + 1], p2[1][2 * kt + 1] };
#pragma unroll
            for (int njp = 0; njp < 16; njp++) {
                u32 r[4];
                ldsm4t(r, smem_a(&sV[(kt * 16 + ((lane >> 3) & 1) * 8 + (lane & 7)) * VLD
                                     + njp * 16 + (lane >> 4) * 8]));
                u32 b0[2] = { r[0], r[1] }, b1[2] = { r[2], r[3] };
                mma16816(o[njp * 2], a, b0);
                mma16816(o[njp * 2 + 1], a, b1);
            }
        }

        __syncthreads();   // all warps done with sV and sK[buf]

        // ---- prefetch: V(kc+1) group first, then K(kc+2) group ----
        if (kc + 1 < NCH) {
            const __half* Vn = Vg + (size_t)(kc + 1) * ACH * V_HD;
#pragma unroll
            for (int r = 0; r < 16; r++) {
                int idx = r * 128 + tid, row = idx >> 5, c = (idx & 31) * 8;
                cp_async16(sV_a + (row * VLD + c) * 2, &Vn[(size_t)row * V_HD + c]);
            }
        }
        cp_commit();
        if (kc + 2 < NCH) {
            const __half* Kn = Kg + (size_t)(kc + 2) * ACH * QK_D;
#pragma unroll
            for (int r = 0; r < 8; r++) {
                int idx = r * 128 + tid, row = idx >> 4, c = (idx & 15) * 8;
                cp_async16(sK_a + ((buf * ACH + row) * KLD + c) * 2, &Kn[(size_t)row * QK_D + c]);
            }
        }
        cp_commit();
    }

    // ---- epilogue ----
#pragma unroll
    for (int i = 0; i < 2; i++) {
        float inv = 1.f / l_i[i];
        int row = qt * AQT + warp * 16 + (lane >> 2) + i * 8;
        size_t base = ((size_t)b * S_LEN + row) * (NH * V_HD) + h * V_HD;
#pragma unroll
        for (int nt = 0; nt < 32; nt++) {
            __half2 hh = __floats2half2_rn(o[nt][2 * i] * inv, o[nt][2 * i + 1] * inv);
            *(__half2*)&g_attn_h[base + nt * 8 + 2 * (lane & 3)] = hh;
        }
    }
}

// ---------------------------------------------------------------------------
// Launch
// ---------------------------------------------------------------------------
extern "C" void kernel_launch(void* const* d_in, const int* in_sizes, int n_in,
                              void* d_out, int out_size)
{
    const float* x         = (const float*)d_in[0];
    const int*   pos       = (const int*)  d_in[1];
    const float* w_dq_w    = (const float*)d_in[2];
    const float* w_dq_b    = (const float*)d_in[3];
    const float* q_norm_w  = (const float*)d_in[4];
    const float* w_uq_qr_w = (const float*)d_in[5];
    const float* w_uq_qr_b = (const float*)d_in[6];
    const float* w_dkv_w   = (const float*)d_in[7];
    const float* w_dkv_b   = (const float*)d_in[8];
    const float* kv_norm_w = (const float*)d_in[9];
    const float* w_ukv_w   = (const float*)d_in[10];
    const float* w_ukv_b   = (const float*)d_in[11];
    const float* w_o_w     = (const float*)d_in[12];
    const float* w_o_b     = (const float*)d_in[13];
    float* out = (float*)d_out;

    static int smem_set = 0;
    if (!smem_set) {
        cudaFuncSetAttribute(attn_h_k, cudaFuncAttributeMaxDynamicSharedMemorySize, SMEM_ATT);
        smem_set = 1;
    }

    // single merged fp32 -> fp16 conversion
    cvt_all_k<<<(CN5 + 255) / 256, 256>>>(x, w_dq_w, w_uq_qr_w, w_dkv_w, w_ukv_w, w_o_w);

    // Q path
    hgemm_k<1, 0><<<dim3(Q_C / HBN, BSROWS / HBM), 256>>>(w_dq_b, (float*)0, Q_C, DIM, (const int*)0);
    rmsnorm_q_k<<<BSROWS, 128>>>(q_norm_w);
    hgemm_k<3, 1><<<dim3(NH * QK_D / HBN, BSROWS / HBM), 256>>>(w_uq_qr_b, (float*)0, NH * QK_D, Q_C, pos);

    // KV path
    hgemm_k<2, 0><<<dim3((KV_C + K_ROPE) / HBN, BSROWS / HBM), 256>>>(w_dkv_b, (float*)0, KV_C + K_ROPE, DIM, (const int*)0);
    kv_post_k<<<BSROWS, 128>>>(kv_norm_w, pos);
    hgemm_k<4, 2><<<dim3(NH * (K_NOPE + V_HD) / HBN, BSROWS / HBM), 256>>>(w_ukv_b, (float*)0, NH * (K_NOPE + V_HD), KV_C, (const int*)0);

    // attention
    attn_h_k<<<dim3(S_LEN / AQT, NH, BATCH), 128, SMEM_ATT>>>();

    // output projection
    hgemm_k<0, 3><<<dim3(DIM / HBN, BSROWS / HBM), 256>>>(w_o_b, out, DIM, NH * V_HD, (const int*)0);
}

// round 12
// speedup vs baseline: 9.1154x; 1.0424x over previous
#include <cuda_runtime.h>
#include <cuda_fp16.h>
#include <cstdint>
#include <math.h>

typedef unsigned int u32;

// ---------------------------------------------------------------------------
// Problem constants
// ---------------------------------------------------------------------------
#define DIM     1024
#define NH      8
#define Q_C     128
#define Q_NOPE  96
#define Q_ROPE  32
#define KV_C    128
#define K_ROPE  64
#define K_NOPE  64
#define V_HD    256
#define S_LEN   2048
#define BATCH   2
#define BSROWS  (BATCH * S_LEN)       // 4096
#define QK_D    128
#define DQKV_N  (Q_C + KV_C + K_ROPE) // 320
#define EPSV    1e-8f
// 1/sqrt(128) * log2(e)  (softmax runs in base-2 domain)
#define QSC     (0.08838834764831845f * 1.4426950408889634f)

// ---------------------------------------------------------------------------
// Scratch (static device globals; no allocation allowed)
// ---------------------------------------------------------------------------
__device__ __half hx     [BSROWS * DIM];
__device__ __half hw_dqkv[DIM * DQKV_N];
__device__ __half hw_uq  [Q_C * (NH * QK_D)];
__device__ __half hw_ukv [KV_C * (NH * (K_NOPE + V_HD))];
__device__ __half hw_o   [(NH * V_HD) * DIM];

__device__ float  g_cq_raw[BSROWS * Q_C];
__device__ __half g_cq_h  [BSROWS * Q_C];
__device__ float  g_ckvkr [BSROWS * (KV_C + K_ROPE)];
__device__ __half g_ckv_h [BSROWS * KV_C];
__device__ __half g_qs    [BATCH * NH * S_LEN * QK_D];   // scaled+roped q
__device__ __half g_ks    [BATCH * NH * S_LEN * QK_D];
__device__ __half g_vs    [BATCH * NH * S_LEN * V_HD];
__device__ __half g_attn_h[BSROWS * (NH * V_HD)];

// ---------------------------------------------------------------------------
// PTX helpers
// ---------------------------------------------------------------------------
__device__ __forceinline__ u32 smem_a(const void* p) {
    return (u32)__cvta_generic_to_shared(p);
}
__device__ __forceinline__ void ldsm4(u32* r, u32 a) {
    asm volatile("ldmatrix.sync.aligned.m8n8.x4.shared.b16 {%0,%1,%2,%3},[%4];"
                 : "=r"(r[0]), "=r"(r[1]), "=r"(r[2]), "=r"(r[3]) : "r"(a));
}
__device__ __forceinline__ void ldsm4t(u32* r, u32 a) {
    asm volatile("ldmatrix.sync.aligned.m8n8.x4.trans.shared.b16 {%0,%1,%2,%3},[%4];"
                 : "=r"(r[0]), "=r"(r[1]), "=r"(r[2]), "=r"(r[3]) : "r"(a));
}
__device__ __forceinline__ void mma16816(float* d, const u32* a, const u32* b) {
    asm volatile("mma.sync.aligned.m16n8k16.row.col.f32.f16.f16.f32 "
                 "{%0,%1,%2,%3},{%4,%5,%6,%7},{%8,%9},{%0,%1,%2,%3};"
                 : "+f"(d[0]), "+f"(d[1]), "+f"(d[2]), "+f"(d[3])
                 : "r"(a[0]), "r"(a[1]), "r"(a[2]), "r"(a[3]), "r"(b[0]), "r"(b[1]));
}
__device__ __forceinline__ void cp_async16(u32 s, const void* g) {
    asm volatile("cp.async.cg.shared.global [%0], [%1], 16;" :: "r"(s), "l"(g));
}
__device__ __forceinline__ void cp_commit() {
    asm volatile("cp.async.commit_group;");
}
template <int N>
__device__ __forceinline__ void cp_wait() {
    asm volatile("cp.async.wait_group %0;" :: "n"(N));
}

// ---------------------------------------------------------------------------
// Merged fp32 -> fp16 conversion (one launch). dq/dkv interleave into hw_dqkv.
// All indices are int4 (8-half) granules.
// ---------------------------------------------------------------------------
#define CN0 (BSROWS * DIM / 8)                         // x
#define CN1 (CN0 + DIM * Q_C / 8)                      // dq  -> hw_dqkv cols 0..127
#define CN2 (CN1 + DIM * (KV_C + K_ROPE) / 8)          // dkv -> hw_dqkv cols 128..319
#define CN3 (CN2 + Q_C * NH * QK_D / 8)                // uq
#define CN4 (CN3 + KV_C * NH * (K_NOPE + V_HD) / 8)    // ukv
#define CN5 (CN4 + NH * V_HD * DIM / 8)                // o

__global__ void cvt_all_k(const float* __restrict__ x,   const float* __restrict__ dq,
                          const float* __restrict__ uq,  const float* __restrict__ dkv,
                          const float* __restrict__ ukv, const float* __restrict__ o)
{
    int i = blockIdx.x * blockDim.x + threadIdx.x;
    if (i >= CN5) return;
    const float* src; __half* dstp; int off;
    if (i < CN0)      { src = x;   off = i;       dstp = hx + (size_t)off * 8; }
    else if (i < CN1) { src = dq;  off = i - CN0;
                        int r = off / 16, c = (off * 8) % Q_C;
                        dstp = hw_dqkv + (size_t)r * DQKV_N + c; }
    else if (i < CN2) { src = dkv; off = i - CN1;
                        int r = off / 24, c = (off * 8) % (KV_C + K_ROPE);
                        dstp = hw_dqkv + (size_t)r * DQKV_N + Q_C + c; }
    else if (i < CN3) { src = uq;  off = i - CN2; dstp = hw_uq  + (size_t)off * 8; }
    else if (i < CN4) { src = ukv; off = i - CN3; dstp = hw_ukv + (size_t)off * 8; }
    else              { src = o;   off = i - CN4; dstp = hw_o   + (size_t)off * 8; }
    float4 f0 = ((const float4*)src)[2 * off];
    float4 f1 = ((const float4*)src)[2 * off + 1];
    union { __half2 h[4]; int4 v; } u;
    u.h[0] = __floats2half2_rn(f0.x, f0.y);
    u.h[1] = __floats2half2_rn(f0.z, f0.w);
    u.h[2] = __floats2half2_rn(f1.x, f1.y);
    u.h[3] = __floats2half2_rn(f1.z, f1.w);
    *(int4*)dstp = u.v;
}

// ---------------------------------------------------------------------------
// Paired epilogue store (n even, pair (n, n+1))
// EPI: 0=out fp32, 1=fused dq+dkv, 3=Q scatter(scaled+roped), 4=KV scatter
// ---------------------------------------------------------------------------
template <int EPI>
__device__ __forceinline__ void epi_pair(int m, int n, float v0, float v1,
                                         float* C, int N, const int* pos)
{
    int b = m / S_LEN, s = m - b * S_LEN;
    if (EPI == 0) {
        *(float2*)&C[(size_t)m * N + n] = make_float2(v0, v1);
    } else if (EPI == 1) {
        if (n < Q_C) *(float2*)&g_cq_raw[m * Q_C + n] = make_float2(v0, v1);
        else *(float2*)&g_ckvkr[m * (KV_C + K_ROPE) + n - Q_C] = make_float2(v0, v1);
    } else if (EPI == 3) {
        int h, d;
        if (n < NH * Q_NOPE) { h = n / Q_NOPE; d = n % Q_NOPE; }
        else { int j = n - NH * Q_NOPE; h = j / Q_ROPE; d = Q_NOPE + (j % Q_ROPE); }
        v0 *= QSC; v1 *= QSC;
        if (d >= Q_NOPE) {   // fused RoPE (pair is exactly (2i, 2i+1))
            float p = (float)pos[b * S_LEN + s];
            float inv = __expf(-((float)(d - Q_NOPE) / (float)Q_ROPE) * 9.210340371976184f);
            float sn, cs;
            __sincosf(p * inv, &sn, &cs);
            float r0 = v0 * cs - v1 * sn;
            float r1 = v0 * sn + v1 * cs;
            v0 = r0; v1 = r1;
        }
        *(__half2*)&g_qs[(((size_t)b * NH + h) * S_LEN + s) * QK_D + d] =
            __floats2half2_rn(v0, v1);
    } else {
        if (n < NH * K_NOPE) {
            int h = n / K_NOPE, d = n % K_NOPE;
            *(__half2*)&g_ks[(((size_t)b * NH + h) * S_LEN + s) * QK_D + d] =
                __floats2half2_rn(v0, v1);
        } else {
            int j = n - NH * K_NOPE;
            int h = j / V_HD, d = j % V_HD;
            *(__half2*)&g_vs[(((size_t)b * NH + h) * S_LEN + s) * V_HD + d] =
                __floats2half2_rn(v0, v1);
        }
    }
}

// ---------------------------------------------------------------------------
// HGEMM: 128x64x32 tile, 256 threads (8 warps 4x2), warp tile 32x32, fp16 mma.
// 2-stage cp.async pipeline: one barrier per K-step, loads overlap mma.
// ---------------------------------------------------------------------------
#define HBM 128
#define HBN 64
#define HBK 32
#define ALD 40
#define BLD 72

template <int EPI, int ASRC>
__global__ void __launch_bounds__(256) hgemm_k(const float* __restrict__ bias,
                                               const float* __restrict__ bias2,
                                               float* __restrict__ C, int N, int K,
                                               const int* __restrict__ pos)
{
    const __half* A = ASRC == 0 ? hx : ASRC == 1 ? g_cq_h : ASRC == 2 ? g_ckv_h : g_attn_h;
    const __half* B = EPI == 1 ? hw_dqkv : EPI == 3 ? hw_uq :
                      EPI == 4 ? hw_ukv : hw_o;

    __shared__ __half sA[2][HBM * ALD];
    __shared__ __half sB[2][HBK * BLD];

    int tid = threadIdx.x, warp = tid >> 5, lane = tid & 31;
    int m0 = blockIdx.y * HBM, n0 = blockIdx.x * HBN;
    int wm = (warp >> 1) * 32, wn = (warp & 1) * 32;

    float acc[2][4][4];
#pragma unroll
    for (int i = 0; i < 2; i++)
#pragma unroll
        for (int j = 0; j < 4; j++)
#pragma unroll
            for (int k = 0; k < 4; k++) acc[i][j][k] = 0.f;

    int ar = tid >> 2, ac = (tid & 3) * 8;   // A: rows 0..63 (+64), 32-col stage
    int br = tid >> 3, bc = (tid & 7) * 8;   // B: rows 0..31, 64-col stage
    u32 sA_a = smem_a(sA), sB_a = smem_a(sB);

    auto load_stage = [&](int st, int k0) {
        cp_async16(sA_a + (((size_t)st * HBM + ar) * ALD + ac) * 2,
                   &A[(size_t)(m0 + ar) * K + k0 + ac]);
        cp_async16(sA_a + (((size_t)st * HBM + 64 + ar) * ALD + ac) * 2,
                   &A[(size_t)(m0 + 64 + ar) * K + k0 + ac]);
        cp_async16(sB_a + (((size_t)st * HBK + br) * BLD + bc) * 2,
                   &B[(size_t)(k0 + br) * N + n0 + bc]);
        cp_commit();
    };

    load_stage(0, 0);
    int nIt = K / HBK;
    for (int it = 0; it < nIt; it++) {
        cp_wait<0>();
        __syncthreads();
        if (it + 1 < nIt) load_stage((it + 1) & 1, (it + 1) * HBK);
        const __half* sAb = sA[it & 1];
        const __half* sBb = sB[it & 1];
#pragma unroll
        for (int ks = 0; ks < 2; ks++) {
            u32 a[2][4], bm[4][2];
#pragma unroll
            for (int mi = 0; mi < 2; mi++)
                ldsm4(a[mi], smem_a(&sAb[(wm + mi * 16 + (lane & 15)) * ALD + ks * 16 + (lane >> 4) * 8]));
#pragma unroll
            for (int njp = 0; njp < 2; njp++) {
                u32 r[4];
                ldsm4t(r, smem_a(&sBb[(ks * 16 + ((lane >> 3) & 1) * 8 + (lane & 7)) * BLD
                                      + wn + njp * 16 + (lane >> 4) * 8]));
                bm[njp * 2][0] = r[0]; bm[njp * 2][1] = r[1];
                bm[njp * 2 + 1][0] = r[2]; bm[njp * 2 + 1][1] = r[3];
            }
#pragma unroll
            for (int mi = 0; mi < 2; mi++)
#pragma unroll
                for (int nj = 0; nj < 4; nj++)
                    mma16816(acc[mi][nj], a[mi], bm[nj]);
        }
    }

#pragma unroll
    for (int mi = 0; mi < 2; mi++)
#pragma unroll
        for (int nj = 0; nj < 4; nj++) {
            int row = m0 + wm + mi * 16 + (lane >> 2);
            int col = n0 + wn + nj * 8 + 2 * (lane & 3);
            float b0, b1;
            if (EPI == 1) {
                b0 = col < Q_C ? bias[col] : bias2[col - Q_C];
                b1 = col + 1 < Q_C ? bias[col + 1] : bias2[col + 1 - Q_C];
            } else {
                b0 = bias[col]; b1 = bias[col + 1];
            }
            epi_pair<EPI>(row,     col, acc[mi][nj][0] + b0, acc[mi][nj][1] + b1, C, N, pos);
            epi_pair<EPI>(row + 8, col, acc[mi][nj][2] + b0, acc[mi][nj][3] + b1, C, N, pos);
        }
}

// ---------------------------------------------------------------------------
// RMSNorm q: fp32 in -> half out
// ---------------------------------------------------------------------------
__global__ void rmsnorm_q_k(const float* __restrict__ w)
{
    int row = blockIdx.x, t = threadIdx.x;
    float v = g_cq_raw[row * Q_C + t];
    float ss = v * v;
#pragma unroll
    for (int off = 16; off > 0; off >>= 1) ss += __shfl_xor_sync(0xffffffffu, ss, off);
    __shared__ float s4[4];
    if ((t & 31) == 0) s4[t >> 5] = ss;
    __syncthreads();
    float tot = s4[0] + s4[1] + s4[2] + s4[3];
    float r = rsqrtf(tot * (1.0f / Q_C) + EPSV);
    g_cq_h[row * Q_C + t] = __float2half(w[t] * v * r);
}

// ---------------------------------------------------------------------------
// KV post: RMSNorm ckv -> half; RoPE k_rope -> broadcast (half) to all heads.
// ---------------------------------------------------------------------------
__global__ void kv_post_k(const float* __restrict__ kvw, const int* __restrict__ pos_ids)
{
    int row = blockIdx.x, t = threadIdx.x;
    const float* src = &g_ckvkr[row * (KV_C + K_ROPE)];
    float v = src[t];
    float ss = v * v;
#pragma unroll
    for (int off = 16; off > 0; off >>= 1) ss += __shfl_xor_sync(0xffffffffu, ss, off);
    __shared__ float s4[4];
    if ((t & 31) == 0) s4[t >> 5] = ss;
    __syncthreads();
    float tot = s4[0] + s4[1] + s4[2] + s4[3];
    float r = rsqrtf(tot * (1.0f / KV_C) + EPSV);
    g_ckv_h[row * KV_C + t] = __float2half(kvw[t] * v * r);

    if (t < K_ROPE / 2) {
        int i = t;
        float xe = src[KV_C + 2 * i];
        float xo = src[KV_C + 2 * i + 1];
        float p = (float)pos_ids[row];
        float inv = expf(-((float)(2 * i) / (float)K_ROPE) * 9.210340371976184f);
        float sn, cs;
        sincosf(p * inv, &sn, &cs);
        __half re = __float2half(xe * cs - xo * sn);
        __half ro = __float2half(xe * sn + xo * cs);
        int b = row / S_LEN, s = row - b * S_LEN;
#pragma unroll
        for (int h = 0; h < NH; h++) {
            size_t base = (((size_t)b * NH + h) * S_LEN + s) * QK_D + K_NOPE;
            g_ks[base + 2 * i]     = re;
            g_ks[base + 2 * i + 1] = ro;
        }
    }
}

// ---------------------------------------------------------------------------
// Flash attention, fp16 mma, base-2 softmax. Grid (32, 8, 2), 128 thr = 4 warps.
// Each warp: 16 query rows x full 256-d output. 64-key chunks.
// Q resident in smem; K double-buffered cp.async; V single-buffered.
// Exact rescale-skip when the running max is unchanged.
// ---------------------------------------------------------------------------
#define AQT 64
#define ACH 64
#define QLD 136
#define KLD 136
#define VLD 264
#define SM_Q (AQT * QLD)
#define SM_K (2 * ACH * KLD)
#define SM_V (ACH * VLD)
#define SMEM_ATT ((SM_Q + SM_K + SM_V) * 2)   // 86016 bytes

__global__ void __launch_bounds__(128) attn_h_k()
{
    extern __shared__ __half dsm[];
    __half* sQ = dsm;                 // [AQT][QLD]
    __half* sK = dsm + SM_Q;          // [2][ACH][KLD]
    __half* sV = dsm + SM_Q + SM_K;   // [ACH][VLD]

    int tid = threadIdx.x, warp = tid >> 5, lane = tid & 31;
    int qt = blockIdx.x, h = blockIdx.y, b = blockIdx.z;

    const __half* Qg = g_qs + (((size_t)b * NH + h) * S_LEN + (size_t)qt * AQT) * QK_D;
    const __half* Kg = g_ks + ((size_t)b * NH + h) * S_LEN * QK_D;
    const __half* Vg = g_vs + ((size_t)b * NH + h) * S_LEN * V_HD;

    u32 sK_a = smem_a(sK), sV_a = smem_a(sV);

    // ---- prologue: K0 group, V0 group, K1 group (commit order matters) ----
#pragma unroll
    for (int r = 0; r < 8; r++) {
        int idx = r * 128 + tid, row = idx >> 4, c = (idx & 15) * 8;
        cp_async16(sK_a + (row * KLD + c) * 2, &Kg[(size_t)row * QK_D + c]);
    }
    cp_commit();
#pragma unroll
    for (int r = 0; r < 16; r++) {
        int idx = r * 128 + tid, row = idx >> 5, c = (idx & 31) * 8;
        cp_async16(sV_a + (row * VLD + c) * 2, &Vg[(size_t)row * V_HD + c]);
    }
    cp_commit();
#pragma unroll
    for (int r = 0; r < 8; r++) {
        int idx = r * 128 + tid, row = idx >> 4, c = (idx & 15) * 8;
        cp_async16(sK_a + ((ACH + row) * KLD + c) * 2, &Kg[(size_t)(ACH + row) * QK_D + c]);
    }
    cp_commit();

    // ---- stage Q (plain stores; visibility via first in-loop barrier) ----
#pragma unroll
    for (int r = 0; r < 8; r++) {
        int idx = r * 128 + tid, row = idx >> 4, c = (idx & 15) * 8;
        *(int4*)&sQ[row * QLD + c] = *(const int4*)&Qg[row * QK_D + c];
    }

    float m_i[2] = { -1e30f, -1e30f }, l_i[2] = { 0.f, 0.f };
    float o[32][4];
#pragma unroll
    for (int nt = 0; nt < 32; nt++)
#pragma unroll
        for (int j = 0; j < 4; j++) o[nt][j] = 0.f;

    const int NCH = S_LEN / ACH;    // 32
    for (int kc = 0; kc < NCH; kc++) {
        int buf = kc & 1;
        cp_wait<1>();          // K(kc) and V(kc) complete (only K(kc+1) pending)
        __syncthreads();

        const __half* sKb = sK + buf * ACH * KLD;

        // ---- scores S = Q K^T (Q pre-scaled by 1/sqrt(d)*log2e) ----
        float sc[8][4];
#pragma unroll
        for (int nj = 0; nj < 8; nj++)
#pragma unroll
            for (int j = 0; j < 4; j++) sc[nj][j] = 0.f;

#pragma unroll
        for (int ks = 0; ks < 8; ks++) {
            u32 qa[4];
            ldsm4(qa, smem_a(&sQ[(warp * 16 + (lane & 15)) * QLD + ks * 16 + (lane >> 4) * 8]));
            u32 bm[8][2];
#pragma unroll
            for (int njp = 0; njp < 4; njp++) {
                u32 r[4];
                ldsm4(r, smem_a(&sKb[(njp * 16 + ((lane >> 4) & 1) * 8 + (lane & 7)) * KLD
                                     + ks * 16 + ((lane >> 3) & 1) * 8]));
                bm[njp * 2][0] = r[0]; bm[njp * 2][1] = r[1];
                bm[njp * 2 + 1][0] = r[2]; bm[njp * 2 + 1][1] = r[3];
            }
#pragma unroll
            for (int nj = 0; nj < 8; nj++) mma16816(sc[nj], qa, bm[nj]);
        }

        // ---- online softmax (base 2), exact rescale-skip ----
        u32 p2[2][8];
#pragma unroll
        for (int i = 0; i < 2; i++) {
            float mx = -1e30f;
#pragma unroll
            for (int nj = 0; nj < 8; nj++)
                mx = fmaxf(mx, fmaxf(sc[nj][2 * i], sc[nj][2 * i + 1]));
            mx = fmaxf(mx, __shfl_xor_sync(0xffffffffu, mx, 1));
            mx = fmaxf(mx, __shfl_xor_sync(0xffffffffu, mx, 2));
            float mn = fmaxf(m_i[i], mx);
            float rs = 0.f;
#pragma unroll
            for (int nj = 0; nj < 8; nj++) {
                float p0 = exp2f(sc[nj][2 * i] - mn);
                float p1 = exp2f(sc[nj][2 * i + 1] - mn);
                rs += p0 + p1;
                __half2 hh = __floats2half2_rn(p0, p1);
                p2[i][nj] = *(u32*)&hh;
            }
            rs += __shfl_xor_sync(0xffffffffu, rs, 1);
            rs += __shfl_xor_sync(0xffffffffu, rs, 2);
            if (mn != m_i[i]) {
                float corr = exp2f(m_i[i] - mn);
                l_i[i] = l_i[i] * corr + rs;
                m_i[i] = mn;
#pragma unroll
                for (int nt = 0; nt < 32; nt++) {
                    o[nt][2 * i] *= corr; o[nt][2 * i + 1] *= corr;
                }
            } else {
                l_i[i] += rs;
            }
        }

        // ---- O += P V ----
#pragma unroll
        for (int kt = 0; kt < 4; kt++) {
            u32 a[4] = { p2[0][2 * kt], p2[1][2 * kt], p2[0][2 * kt + 1], p2[1][2 * kt + 1] };
#pragma unroll
            for (int njp = 0; njp < 16; njp++) {
                u32 r[4];
                ldsm4t(r, smem_a(&sV[(kt * 16 + ((lane >> 3) & 1) * 8 + (lane & 7)) * VLD
                                     + njp * 16 + (lane >> 4) * 8]));
                u32 b0[2] = { r[0], r[1] }, b1[2] = { r[2], r[3] };
                mma16816(o[njp * 2], a, b0);
                mma16816(o[njp * 2 + 1], a, b1);
            }
        }

        __syncthreads();   // all warps done with sV and sK[buf]

        // ---- prefetch: V(kc+1) group first, then K(kc+2) group ----
        if (kc + 1 < NCH) {
            const __half* Vn = Vg + (size_t)(kc + 1) * ACH * V_HD;
#pragma unroll
            for (int r = 0; r < 16; r++) {
                int idx = r * 128 + tid, row = idx >> 5, c = (idx & 31) * 8;
                cp_async16(sV_a + (row * VLD + c) * 2, &Vn[(size_t)row * V_HD + c]);
            }
        }
        cp_commit();
        if (kc + 2 < NCH) {
            const __half* Kn = Kg + (size_t)(kc + 2) * ACH * QK_D;
#pragma unroll
            for (int r = 0; r < 8; r++) {
                int idx = r * 128 + tid, row = idx >> 4, c = (idx & 15) * 8;
                cp_async16(sK_a + ((buf * ACH + row) * KLD + c) * 2, &Kn[(size_t)row * QK_D + c]);
            }
        }
        cp_commit();
    }

    // ---- epilogue ----
#pragma unroll
    for (int i = 0; i < 2; i++) {
        float inv = 1.f / l_i[i];
        int row = qt * AQT + warp * 16 + (lane >> 2) + i * 8;
        size_t base = ((size_t)b * S_LEN + row) * (NH * V_HD) + h * V_HD;
#pragma unroll
        for (int nt = 0; nt < 32; nt++) {
            __half2 hh = __floats2half2_rn(o[nt][2 * i] * inv, o[nt][2 * i + 1] * inv);
            *(__half2*)&g_attn_h[base + nt * 8 + 2 * (lane & 3)] = hh;
        }
    }
}

// ---------------------------------------------------------------------------
// Launch
// ---------------------------------------------------------------------------
extern "C" void kernel_launch(void* const* d_in, const int* in_sizes, int n_in,
                              void* d_out, int out_size)
{
    const float* x         = (const float*)d_in[0];
    const int*   pos       = (const int*)  d_in[1];
    const float* w_dq_w    = (const float*)d_in[2];
    const float* w_dq_b    = (const float*)d_in[3];
    const float* q_norm_w  = (const float*)d_in[4];
    const float* w_uq_qr_w = (const float*)d_in[5];
    const float* w_uq_qr_b = (const float*)d_in[6];
    const float* w_dkv_w   = (const float*)d_in[7];
    const float* w_dkv_b   = (const float*)d_in[8];
    const float* kv_norm_w = (const float*)d_in[9];
    const float* w_ukv_w   = (const float*)d_in[10];
    const float* w_ukv_b   = (const float*)d_in[11];
    const float* w_o_w     = (const float*)d_in[12];
    const float* w_o_b     = (const float*)d_in[13];
    float* out = (float*)d_out;

    static int smem_set = 0;
    if (!smem_set) {
        cudaFuncSetAttribute(attn_h_k, cudaFuncAttributeMaxDynamicSharedMemorySize, SMEM_ATT);
        smem_set = 1;
    }

    // single merged fp32 -> fp16 conversion (dq/dkv fuse into hw_dqkv)
    cvt_all_k<<<(CN5 + 255) / 256, 256>>>(x, w_dq_w, w_uq_qr_w, w_dkv_w, w_ukv_w, w_o_w);

    // fused dq+dkv down-projection (N=320)
    hgemm_k<1, 0><<<dim3(DQKV_N / HBN, BSROWS / HBM), 256>>>(w_dq_b, w_dkv_b, (float*)0, DQKV_N, DIM, (const int*)0);

    // Q path
    rmsnorm_q_k<<<BSROWS, 128>>>(q_norm_w);
    hgemm_k<3, 1><<<dim3(NH * QK_D / HBN, BSROWS / HBM), 256>>>(w_uq_qr_b, (const float*)0, (float*)0, NH * QK_D, Q_C, pos);

    // KV path
    kv_post_k<<<BSROWS, 128>>>(kv_norm_w, pos);
    hgemm_k<4, 2><<<dim3(NH * (K_NOPE + V_HD) / HBN, BSROWS / HBM), 256>>>(w_ukv_b, (const float*)0, (float*)0, NH * (K_NOPE + V_HD), KV_C, (const int*)0);

    // attention
    attn_h_k<<<dim3(S_LEN / AQT, NH, BATCH), 128, SMEM_ATT>>>();

    // output projection
    hgemm_k<0, 3><<<dim3(DIM / HBN, BSROWS / HBM), 256>>>(w_o_b, (const float*)0, out, DIM, NH * V_HD, (const int*)0);
}

// round 14
// speedup vs baseline: 9.4462x; 1.0363x over previous
#include <cuda_runtime.h>
#include <cuda_fp16.h>
#include <cstdint>
#include <math.h>

typedef unsigned int u32;

// ---------------------------------------------------------------------------
// Problem constants
// ---------------------------------------------------------------------------
#define DIM     1024
#define NH      8
#define Q_C     128
#define Q_NOPE  96
#define Q_ROPE  32
#define KV_C    128
#define K_ROPE  64
#define K_NOPE  64
#define V_HD    256
#define S_LEN   2048
#define BATCH   2
#define BSROWS  (BATCH * S_LEN)       // 4096
#define QK_D    128
#define DQKV_N  (Q_C + KV_C + K_ROPE) // 320
#define EPSV    1e-8f
// 1/sqrt(128) * log2(e)  (softmax runs in base-2 domain)
#define QSC     (0.08838834764831845f * 1.4426950408889634f)

// ---------------------------------------------------------------------------
// Scratch (static device globals; no allocation allowed)
// ---------------------------------------------------------------------------
__device__ __half hx     [BSROWS * DIM];
__device__ __half hw_dqkv[DIM * DQKV_N];
__device__ __half hw_uq  [Q_C * (NH * QK_D)];
__device__ __half hw_ukv [KV_C * (NH * (K_NOPE + V_HD))];
__device__ __half hw_o   [(NH * V_HD) * DIM];

__device__ float  g_cq_raw[BSROWS * Q_C];
__device__ __half g_cq_h  [BSROWS * Q_C];
__device__ float  g_ckvkr [BSROWS * (KV_C + K_ROPE)];
__device__ __half g_ckv_h [BSROWS * KV_C];
__device__ __half g_qs    [BATCH * NH * S_LEN * QK_D];   // scaled+roped q
__device__ __half g_ks    [BATCH * NH * S_LEN * QK_D];
__device__ __half g_vs    [BATCH * NH * S_LEN * V_HD];
__device__ __half g_attn_h[BSROWS * (NH * V_HD)];

// ---------------------------------------------------------------------------
// PTX helpers
// ---------------------------------------------------------------------------
__device__ __forceinline__ u32 smem_a(const void* p) {
    return (u32)__cvta_generic_to_shared(p);
}
__device__ __forceinline__ void ldsm4(u32* r, u32 a) {
    asm volatile("ldmatrix.sync.aligned.m8n8.x4.shared.b16 {%0,%1,%2,%3},[%4];"
                 : "=r"(r[0]), "=r"(r[1]), "=r"(r[2]), "=r"(r[3]) : "r"(a));
}
__device__ __forceinline__ void ldsm4t(u32* r, u32 a) {
    asm volatile("ldmatrix.sync.aligned.m8n8.x4.trans.shared.b16 {%0,%1,%2,%3},[%4];"
                 : "=r"(r[0]), "=r"(r[1]), "=r"(r[2]), "=r"(r[3]) : "r"(a));
}
__device__ __forceinline__ void mma16816(float* d, const u32* a, const u32* b) {
    asm volatile("mma.sync.aligned.m16n8k16.row.col.f32.f16.f16.f32 "
                 "{%0,%1,%2,%3},{%4,%5,%6,%7},{%8,%9},{%0,%1,%2,%3};"
                 : "+f"(d[0]), "+f"(d[1]), "+f"(d[2]), "+f"(d[3])
                 : "r"(a[0]), "r"(a[1]), "r"(a[2]), "r"(a[3]), "r"(b[0]), "r"(b[1]));
}
__device__ __forceinline__ void cp_async16(u32 s, const void* g) {
    asm volatile("cp.async.cg.shared.global [%0], [%1], 16;" :: "r"(s), "l"(g));
}
__device__ __forceinline__ void cp_commit() {
    asm volatile("cp.async.commit_group;");
}
template <int N>
__device__ __forceinline__ void cp_wait() {
    asm volatile("cp.async.wait_group %0;" :: "n"(N));
}

// ---------------------------------------------------------------------------
// Merged fp32 -> fp16 conversion (one launch). dq/dkv interleave into hw_dqkv.
// ---------------------------------------------------------------------------
#define CN0 (BSROWS * DIM / 8)                         // x
#define CN1 (CN0 + DIM * Q_C / 8)                      // dq  -> hw_dqkv cols 0..127
#define CN2 (CN1 + DIM * (KV_C + K_ROPE) / 8)          // dkv -> hw_dqkv cols 128..319
#define CN3 (CN2 + Q_C * NH * QK_D / 8)                // uq
#define CN4 (CN3 + KV_C * NH * (K_NOPE + V_HD) / 8)    // ukv
#define CN5 (CN4 + NH * V_HD * DIM / 8)                // o

__global__ void cvt_all_k(const float* __restrict__ x,   const float* __restrict__ dq,
                          const float* __restrict__ uq,  const float* __restrict__ dkv,
                          const float* __restrict__ ukv, const float* __restrict__ o)
{
    int i = blockIdx.x * blockDim.x + threadIdx.x;
    if (i >= CN5) return;
    const float* src; __half* dstp; int off;
    if (i < CN0)      { src = x;   off = i;       dstp = hx + (size_t)off * 8; }
    else if (i < CN1) { src = dq;  off = i - CN0;
                        int r = off / 16, c = (off * 8) % Q_C;
                        dstp = hw_dqkv + (size_t)r * DQKV_N + c; }
    else if (i < CN2) { src = dkv; off = i - CN1;
                        int r = off / 24, c = (off * 8) % (KV_C + K_ROPE);
                        dstp = hw_dqkv + (size_t)r * DQKV_N + Q_C + c; }
    else if (i < CN3) { src = uq;  off = i - CN2; dstp = hw_uq  + (size_t)off * 8; }
    else if (i < CN4) { src = ukv; off = i - CN3; dstp = hw_ukv + (size_t)off * 8; }
    else              { src = o;   off = i - CN4; dstp = hw_o   + (size_t)off * 8; }
    float4 f0 = ((const float4*)src)[2 * off];
    float4 f1 = ((const float4*)src)[2 * off + 1];
    union { __half2 h[4]; int4 v; } u;
    u.h[0] = __floats2half2_rn(f0.x, f0.y);
    u.h[1] = __floats2half2_rn(f0.z, f0.w);
    u.h[2] = __floats2half2_rn(f1.x, f1.y);
    u.h[3] = __floats2half2_rn(f1.z, f1.w);
    *(int4*)dstp = u.v;
}

// ---------------------------------------------------------------------------
// HGEMM: 128x64x32 tile, 256 threads (8 warps 4x2), warp tile 32x32, fp16 mma.
// 3-stage cp.async pipeline. Coalesced epilogue via smem staging (EPI 1/3/4).
// EPI: 0=out fp32 direct, 1=fused dq+dkv (fp32), 3=Q scatter, 4=KV scatter
// ---------------------------------------------------------------------------
#define HBM 128
#define HBN 64
#define HBK 32
#define ALD 40
#define BLD 72
#define NSTG 3
#define A_STG (HBM * ALD)        // halfs per A stage
#define B_STG (HBK * BLD)        // halfs per B stage
#define SMEM_HG (NSTG * (A_STG + B_STG) * 2)   // 44544 bytes
#define FSTRIDE 68               // float staging row stride
#define HSTRIDE 72               // half staging row stride

template <int EPI, int ASRC>
__global__ void __launch_bounds__(256) hgemm_k(const float* __restrict__ bias,
                                               const float* __restrict__ bias2,
                                               float* __restrict__ C, int N, int K,
                                               const int* __restrict__ pos)
{
    const __half* A = ASRC == 0 ? hx : ASRC == 1 ? g_cq_h : ASRC == 2 ? g_ckv_h : g_attn_h;
    const __half* B = EPI == 1 ? hw_dqkv : EPI == 3 ? hw_uq :
                      EPI == 4 ? hw_ukv : hw_o;

    __shared__ __align__(16) char smem_raw[SMEM_HG];
    __half* sA = (__half*)smem_raw;                      // [NSTG][HBM][ALD]
    __half* sB = (__half*)smem_raw + NSTG * A_STG;       // [NSTG][HBK][BLD]

    int tid = threadIdx.x, warp = tid >> 5, lane = tid & 31;
    int m0 = blockIdx.y * HBM, n0 = blockIdx.x * HBN;
    int wm = (warp >> 1) * 32, wn = (warp & 1) * 32;

    float acc[2][4][4];
#pragma unroll
    for (int i = 0; i < 2; i++)
#pragma unroll
        for (int j = 0; j < 4; j++)
#pragma unroll
            for (int k = 0; k < 4; k++) acc[i][j][k] = 0.f;

    int ar = tid >> 2, ac = (tid & 3) * 8;
    int br = tid >> 3, bc = (tid & 7) * 8;
    u32 sA_a = smem_a(sA), sB_a = smem_a(sB);

    auto load_stage = [&](int st, int k0) {
        cp_async16(sA_a + (((size_t)st * HBM + ar) * ALD + ac) * 2,
                   &A[(size_t)(m0 + ar) * K + k0 + ac]);
        cp_async16(sA_a + (((size_t)st * HBM + 64 + ar) * ALD + ac) * 2,
                   &A[(size_t)(m0 + 64 + ar) * K + k0 + ac]);
        cp_async16(sB_a + (((size_t)st * HBK + br) * BLD + bc) * 2,
                   &B[(size_t)(k0 + br) * N + n0 + bc]);
        cp_commit();
    };

    int nIt = K / HBK;
    load_stage(0, 0);
    load_stage(1, HBK);
    for (int it = 0; it < nIt; it++) {
        cp_wait<1>();
        __syncthreads();
        if (it + 2 < nIt) load_stage((it + 2) % NSTG, (it + 2) * HBK);
        else cp_commit();   // keep group count advancing so wait<1> pins stage it
        int st = it % NSTG;
        const __half* sAb = sA + st * A_STG;
        const __half* sBb = sB + st * B_STG;
#pragma unroll
        for (int ks = 0; ks < 2; ks++) {
            u32 a[2][4], bm[4][2];
#pragma unroll
            for (int mi = 0; mi < 2; mi++)
                ldsm4(a[mi], smem_a(&sAb[(wm + mi * 16 + (lane & 15)) * ALD + ks * 16 + (lane >> 4) * 8]));
#pragma unroll
            for (int njp = 0; njp < 2; njp++) {
                u32 r[4];
                ldsm4t(r, smem_a(&sBb[(ks * 16 + ((lane >> 3) & 1) * 8 + (lane & 7)) * BLD
                                      + wn + njp * 16 + (lane >> 4) * 8]));
                bm[njp * 2][0] = r[0]; bm[njp * 2][1] = r[1];
                bm[njp * 2 + 1][0] = r[2]; bm[njp * 2 + 1][1] = r[3];
            }
#pragma unroll
            for (int mi = 0; mi < 2; mi++)
#pragma unroll
                for (int nj = 0; nj < 4; nj++)
                    mma16816(acc[mi][nj], a[mi], bm[nj]);
        }
    }

    // ------------------------- epilogue -------------------------
    if (EPI == 0) {
        // direct fp32 stores (K large here; epilogue amortized)
#pragma unroll
        for (int mi = 0; mi < 2; mi++)
#pragma unroll
            for (int nj = 0; nj < 4; nj++) {
                int row = m0 + wm + mi * 16 + (lane >> 2);
                int col = n0 + wn + nj * 8 + 2 * (lane & 3);
                float b0 = bias[col], b1 = bias[col + 1];
                *(float2*)&C[(size_t)row * N + col] =
                    make_float2(acc[mi][nj][0] + b0, acc[mi][nj][1] + b1);
                *(float2*)&C[(size_t)(row + 8) * N + col] =
                    make_float2(acc[mi][nj][2] + b0, acc[mi][nj][3] + b1);
            }
        return;
    }

    __syncthreads();   // done reading pipeline smem; reuse for staging

    if (EPI == 1) {
        float* st = (float*)smem_raw;   // [128][FSTRIDE]
#pragma unroll
        for (int mi = 0; mi < 2; mi++)
#pragma unroll
            for (int nj = 0; nj < 4; nj++) {
                int rl = wm + mi * 16 + (lane >> 2);
                int cl = wn + nj * 8 + 2 * (lane & 3);
                int col = n0 + cl;
                float b0 = col < Q_C ? bias[col] : bias2[col - Q_C];
                float b1 = col + 1 < Q_C ? bias[col + 1] : bias2[col + 1 - Q_C];
                st[rl * FSTRIDE + cl]           = acc[mi][nj][0] + b0;
                st[rl * FSTRIDE + cl + 1]       = acc[mi][nj][1] + b1;
                st[(rl + 8) * FSTRIDE + cl]     = acc[mi][nj][2] + b0;
                st[(rl + 8) * FSTRIDE + cl + 1] = acc[mi][nj][3] + b1;
            }
        __syncthreads();
#pragma unroll
        for (int k = 0; k < 8; k++) {
            int idx = k * 256 + tid;
            int r = idx >> 4, c4 = (idx & 15) * 4;
            float4 v = *(float4*)&st[r * FSTRIDE + c4];
            int m = m0 + r, n = n0 + c4;
            if (n < Q_C) *(float4*)&g_cq_raw[(size_t)m * Q_C + n] = v;
            else *(float4*)&g_ckvkr[(size_t)m * (KV_C + K_ROPE) + n - Q_C] = v;
        }
        return;
    }

    // EPI 3 / 4: half staging with fused scale/rope (EPI 3)
    {
        __half* st = (__half*)smem_raw;   // [128][HSTRIDE]
#pragma unroll
        for (int mi = 0; mi < 2; mi++)
#pragma unroll
            for (int nj = 0; nj < 4; nj++) {
                int rl = wm + mi * 16 + (lane >> 2);
                int cl = wn + nj * 8 + 2 * (lane & 3);
                int col = n0 + cl;
                float b0 = bias[col], b1 = bias[col + 1];
#pragma unroll
                for (int rr = 0; rr < 2; rr++) {
                    float v0 = acc[mi][nj][2 * rr]     + b0;
                    float v1 = acc[mi][nj][2 * rr + 1] + b1;
                    if (EPI == 3) {
                        v0 *= QSC; v1 *= QSC;
                        if (col >= NH * Q_NOPE) {
                            int d = (col - NH * Q_NOPE) % Q_ROPE;  // pair (2i,2i+1)
                            int m = m0 + rl + rr * 8;
                            int b = m / S_LEN, s = m - b * S_LEN;
                            float p = (float)pos[b * S_LEN + s];
                            float inv = __expf(-((float)d / (float)Q_ROPE) * 9.210340371976184f);
                            float sn, cs;
                            __sincosf(p * inv, &sn, &cs);
                            float r0 = v0 * cs - v1 * sn;
                            float r1 = v0 * sn + v1 * cs;
                            v0 = r0; v1 = r1;
                        }
                    }
                    *(__half2*)&st[(rl + rr * 8) * HSTRIDE + cl] = __floats2half2_rn(v0, v1);
                }
            }
        __syncthreads();
#pragma unroll
        for (int k = 0; k < 4; k++) {
            int idx = k * 256 + tid;
            int r = idx >> 3, c8 = (idx & 7) * 8;
            int4 v = *(int4*)&st[r * HSTRIDE + c8];
            int m = m0 + r, n = n0 + c8;
            int b = m / S_LEN, s = m - b * S_LEN;
            if (EPI == 3) {
                int h, d;
                if (n < NH * Q_NOPE) { h = n / Q_NOPE; d = n % Q_NOPE; }
                else { int j = n - NH * Q_NOPE; h = j / Q_ROPE; d = Q_NOPE + (j % Q_ROPE); }
                *(int4*)&g_qs[(((size_t)b * NH + h) * S_LEN + s) * QK_D + d] = v;
            } else {
                if (n < NH * K_NOPE) {
                    int h = n / K_NOPE, d = n % K_NOPE;
                    *(int4*)&g_ks[(((size_t)b * NH + h) * S_LEN + s) * QK_D + d] = v;
                } else {
                    int j = n - NH * K_NOPE;
                    int h = j / V_HD, d = j % V_HD;
                    *(int4*)&g_vs[(((size_t)b * NH + h) * S_LEN + s) * V_HD + d] = v;
                }
            }
        }
    }
}

// ---------------------------------------------------------------------------
// Merged norms: warps 0-3 do q RMSNorm, warps 4-7 do kv RMSNorm + k rope.
// One block (256 thr) per row.
// ---------------------------------------------------------------------------
__global__ void norms_k(const float* __restrict__ qw, const float* __restrict__ kvw,
                        const int* __restrict__ pos_ids)
{
    int row = blockIdx.x, t = threadIdx.x;
    __shared__ float s8[8];
    if (t < 128) {
        float v = g_cq_raw[row * Q_C + t];
        float ss = v * v;
#pragma unroll
        for (int off = 16; off > 0; off >>= 1) ss += __shfl_xor_sync(0xffffffffu, ss, off);
        if ((t & 31) == 0) s8[t >> 5] = ss;
        __syncthreads();
        float tot = s8[0] + s8[1] + s8[2] + s8[3];
        float r = rsqrtf(tot * (1.0f / Q_C) + EPSV);
        g_cq_h[row * Q_C + t] = __float2half(qw[t] * v * r);
    } else {
        int tk = t - 128;
        const float* src = &g_ckvkr[row * (KV_C + K_ROPE)];
        float v = src[tk];
        float ss = v * v;
#pragma unroll
        for (int off = 16; off > 0; off >>= 1) ss += __shfl_xor_sync(0xffffffffu, ss, off);
        if ((tk & 31) == 0) s8[4 + (tk >> 5)] = ss;
        __syncthreads();
        float tot = s8[4] + s8[5] + s8[6] + s8[7];
        float r = rsqrtf(tot * (1.0f / KV_C) + EPSV);
        g_ckv_h[row * KV_C + tk] = __float2half(kvw[tk] * v * r);

        if (tk < K_ROPE / 2) {
            int i = tk;
            float xe = src[KV_C + 2 * i];
            float xo = src[KV_C + 2 * i + 1];
            float p = (float)pos_ids[row];
            float inv = expf(-((float)(2 * i) / (float)K_ROPE) * 9.210340371976184f);
            float sn, cs;
            sincosf(p * inv, &sn, &cs);
            __half re = __float2half(xe * cs - xo * sn);
            __half ro = __float2half(xe * sn + xo * cs);
            int b = row / S_LEN, s = row - b * S_LEN;
#pragma unroll
            for (int h = 0; h < NH; h++) {
                size_t base = (((size_t)b * NH + h) * S_LEN + s) * QK_D + K_NOPE;
                g_ks[base + 2 * i]     = re;
                g_ks[base + 2 * i + 1] = ro;
            }
        }
    }
}

// ---------------------------------------------------------------------------
// Flash attention, fp16 mma, base-2 softmax. Grid (32, 8, 2), 128 thr = 4 warps.
// Each warp: 16 query rows x full 256-d output. 64-key chunks.
// Q resident in smem; K double-buffered cp.async; V single-buffered.
// Exact rescale-skip when the running max is unchanged.
// ---------------------------------------------------------------------------
#define AQT 64
#define ACH 64
#define QLD 136
#define KLD 136
#define VLD 264
#define SM_Q (AQT * QLD)
#define SM_K (2 * ACH * KLD)
#define SM_V (ACH * VLD)
#define SMEM_ATT ((SM_Q + SM_K + SM_V) * 2)   // 86016 bytes

__global__ void __launch_bounds__(128) attn_h_k()
{
    extern __shared__ __half dsm[];
    __half* sQ = dsm;                 // [AQT][QLD]
    __half* sK = dsm + SM_Q;          // [2][ACH][KLD]
    __half* sV = dsm + SM_Q + SM_K;   // [ACH][VLD]

    int tid = threadIdx.x, warp = tid >> 5, lane = tid & 31;
    int qt = blockIdx.x, h = blockIdx.y, b = blockIdx.z;

    const __half* Qg = g_qs + (((size_t)b * NH + h) * S_LEN + (size_t)qt * AQT) * QK_D;
    const __half* Kg = g_ks + ((size_t)b * NH + h) * S_LEN * QK_D;
    const __half* Vg = g_vs + ((size_t)b * NH + h) * S_LEN * V_HD;

    u32 sK_a = smem_a(sK), sV_a = smem_a(sV);

    // ---- prologue: K0 group, V0 group, K1 group (commit order matters) ----
#pragma unroll
    for (int r = 0; r < 8; r++) {
        int idx = r * 128 + tid, row = idx >> 4, c = (idx & 15) * 8;
        cp_async16(sK_a + (row * KLD + c) * 2, &Kg[(size_t)row * QK_D + c]);
    }
    cp_commit();
#pragma unroll
    for (int r = 0; r < 16; r++) {
        int idx = r * 128 + tid, row = idx >> 5, c = (idx & 31) * 8;
        cp_async16(sV_a + (row * VLD + c) * 2, &Vg[(size_t)row * V_HD + c]);
    }
    cp_commit();
#pragma unroll
    for (int r = 0; r < 8; r++) {
        int idx = r * 128 + tid, row = idx >> 4, c = (idx & 15) * 8;
        cp_async16(sK_a + ((ACH + row) * KLD + c) * 2, &Kg[(size_t)(ACH + row) * QK_D + c]);
    }
    cp_commit();

    // ---- stage Q (plain stores; visibility via first in-loop barrier) ----
#pragma unroll
    for (int r = 0; r < 8; r++) {
        int idx = r * 128 + tid, row = idx >> 4, c = (idx & 15) * 8;
        *(int4*)&sQ[row * QLD + c] = *(const int4*)&Qg[row * QK_D + c];
    }

    float m_i[2] = { -1e30f, -1e30f }, l_i[2] = { 0.f, 0.f };
    float o[32][4];
#pragma unroll
    for (int nt = 0; nt < 32; nt++)
#pragma unroll
        for (int j = 0; j < 4; j++) o[nt][j] = 0.f;

    const int NCH = S_LEN / ACH;    // 32
    for (int kc = 0; kc < NCH; kc++) {
        int buf = kc & 1;
        cp_wait<1>();          // K(kc) and V(kc) complete (only K(kc+1) pending)
        __syncthreads();

        const __half* sKb = sK + buf * ACH * KLD;

        // ---- scores S = Q K^T (Q pre-scaled by 1/sqrt(d)*log2e) ----
        float sc[8][4];
#pragma unroll
        for (int nj = 0; nj < 8; nj++)
#pragma unroll
            for (int j = 0; j < 4; j++) sc[nj][j] = 0.f;

#pragma unroll
        for (int ks = 0; ks < 8; ks++) {
            u32 qa[4];
            ldsm4(qa, smem_a(&sQ[(warp * 16 + (lane & 15)) * QLD + ks * 16 + (lane >> 4) * 8]));
            u32 bm[8][2];
#pragma unroll
            for (int njp = 0; njp < 4; njp++) {
                u32 r[4];
                ldsm4(r, smem_a(&sKb[(njp * 16 + ((lane >> 4) & 1) * 8 + (lane & 7)) * KLD
                                     + ks * 16 + ((lane >> 3) & 1) * 8]));
                bm[njp * 2][0] = r[0]; bm[njp * 2][1] = r[1];
                bm[njp * 2 + 1][0] = r[2]; bm[njp * 2 + 1][1] = r[3];
            }
#pragma unroll
            for (int nj = 0; nj < 8; nj++) mma16816(sc[nj], qa, bm[nj]);
        }

        // ---- online softmax (base 2), exact rescale-skip ----
        u32 p2[2][8];
#pragma unroll
        for (int i = 0; i < 2; i++) {
            float mx = -1e30f;
#pragma unroll
            for (int nj = 0; nj < 8; nj++)
                mx = fmaxf(mx, fmaxf(sc[nj][2 * i], sc[nj][2 * i + 1]));
            mx = fmaxf(mx, __shfl_xor_sync(0xffffffffu, mx, 1));
            mx = fmaxf(mx, __shfl_xor_sync(0xffffffffu, mx, 2));
            float mn = fmaxf(m_i[i], mx);
            float rs = 0.f;
#pragma unroll
            for (int nj = 0; nj < 8; nj++) {
                float p0 = exp2f(sc[nj][2 * i] - mn);
                float p1 = exp2f(sc[nj][2 * i + 1] - mn);
                rs += p0 + p1;
                __half2 hh = __floats2half2_rn(p0, p1);
                p2[i][nj] = *(u32*)&hh;
            }
            rs += __shfl_xor_sync(0xffffffffu, rs, 1);
            rs += __shfl_xor_sync(0xffffffffu, rs, 2);
            if (mn != m_i[i]) {
                float corr = exp2f(m_i[i] - mn);
                l_i[i] = l_i[i] * corr + rs;
                m_i[i] = mn;
#pragma unroll
                for (int nt = 0; nt < 32; nt++) {
                    o[nt][2 * i] *= corr; o[nt][2 * i + 1] *= corr;
                }
            } else {
                l_i[i] += rs;
            }
        }

        // ---- O += P V ----
#pragma unroll
        for (int kt = 0; kt < 4; kt++) {
            u32 a[4] = { p2[0][2 * kt], p2[1][2 * kt], p2[0][2 * kt + 1], p2[1][2 * kt + 1] };
#pragma unroll
            for (int njp = 0; njp < 16; njp++) {
                u32 r[4];
                ldsm4t(r, smem_a(&sV[(kt * 16 + ((lane >> 3) & 1) * 8 + (lane & 7)) * VLD
                                     + njp * 16 + (lane >> 4) * 8]));
                u32 b0[2] = { r[0], r[1] }, b1[2] = { r[2], r[3] };
                mma16816(o[njp * 2], a, b0);
                mma16816(o[njp * 2 + 1], a, b1);
            }
        }

        __syncthreads();   // all warps done with sV and sK[buf]

        // ---- prefetch: V(kc+1) group first, then K(kc+2) group ----
        if (kc + 1 < NCH) {
            const __half* Vn = Vg + (size_t)(kc + 1) * ACH * V_HD;
#pragma unroll
            for (int r = 0; r < 16; r++) {
                int idx = r * 128 + tid, row = idx >> 5, c = (idx & 31) * 8;
                cp_async16(sV_a + (row * VLD + c) * 2, &Vn[(size_t)row * V_HD + c]);
            }
        }
        cp_commit();
        if (kc + 2 < NCH) {
            const __half* Kn = Kg + (size_t)(kc + 2) * ACH * QK_D;
#pragma unroll
            for (int r = 0; r < 8; r++) {
                int idx = r * 128 + tid, row = idx >> 4, c = (idx & 15) * 8;
                cp_async16(sK_a + ((buf * ACH + row) * KLD + c) * 2, &Kn[(size_t)row * QK_D + c]);
            }
        }
        cp_commit();
    }

    // ---- epilogue ----
#pragma unroll
    for (int i = 0; i < 2; i++) {
        float inv = 1.f / l_i[i];
        int row = qt * AQT + warp * 16 + (lane >> 2) + i * 8;
        size_t base = ((size_t)b * S_LEN + row) * (NH * V_HD) + h * V_HD;
#pragma unroll
        for (int nt = 0; nt < 32; nt++) {
            __half2 hh = __floats2half2_rn(o[nt][2 * i] * inv, o[nt][2 * i + 1] * inv);
            *(__half2*)&g_attn_h[base + nt * 8 + 2 * (lane & 3)] = hh;
        }
    }
}

// ---------------------------------------------------------------------------
// Launch
// ---------------------------------------------------------------------------
extern "C" void kernel_launch(void* const* d_in, const int* in_sizes, int n_in,
                              void* d_out, int out_size)
{
    const float* x         = (const float*)d_in[0];
    const int*   pos       = (const int*)  d_in[1];
    const float* w_dq_w    = (const float*)d_in[2];
    const float* w_dq_b    = (const float*)d_in[3];
    const float* q_norm_w  = (const float*)d_in[4];
    const float* w_uq_qr_w = (const float*)d_in[5];
    const float* w_uq_qr_b = (const float*)d_in[6];
    const float* w_dkv_w   = (const float*)d_in[7];
    const float* w_dkv_b   = (const float*)d_in[8];
    const float* kv_norm_w = (const float*)d_in[9];
    const float* w_ukv_w   = (const float*)d_in[10];
    const float* w_ukv_b   = (const float*)d_in[11];
    const float* w_o_w     = (const float*)d_in[12];
    const float* w_o_b     = (const float*)d_in[13];
    float* out = (float*)d_out;

    static int smem_set = 0;
    if (!smem_set) {
        cudaFuncSetAttribute(attn_h_k, cudaFuncAttributeMaxDynamicSharedMemorySize, SMEM_ATT);
        smem_set = 1;
    }

    // single merged fp32 -> fp16 conversion (dq/dkv fuse into hw_dqkv)
    cvt_all_k<<<(CN5 + 255) / 256, 256>>>(x, w_dq_w, w_uq_qr_w, w_dkv_w, w_ukv_w, w_o_w);

    // fused dq+dkv down-projection (N=320)
    hgemm_k<1, 0><<<dim3(DQKV_N / HBN, BSROWS / HBM), 256>>>(w_dq_b, w_dkv_b, (float*)0, DQKV_N, DIM, (const int*)0);

    // merged RMSNorms (+ k rope broadcast)
    norms_k<<<BSROWS, 256>>>(q_norm_w, kv_norm_w, pos);

    // up-projections
    hgemm_k<3, 1><<<dim3(NH * QK_D / HBN, BSROWS / HBM), 256>>>(w_uq_qr_b, (const float*)0, (float*)0, NH * QK_D, Q_C, pos);
    hgemm_k<4, 2><<<dim3(NH * (K_NOPE + V_HD) / HBN, BSROWS / HBM), 256>>>(w_ukv_b, (const float*)0, (float*)0, NH * (K_NOPE + V_HD), KV_C, (const int*)0);

    // attention
    attn_h_k<<<dim3(S_LEN / AQT, NH, BATCH), 128, SMEM_ATT>>>();

    // output projection
    hgemm_k<0, 3><<<dim3(DIM / HBN, BSROWS / HBM), 256>>>(w_o_b, (const float*)0, out, DIM, NH * V_HD, (const int*)0);
}